// round 11
// baseline (speedup 1.0000x reference)
#include <cuda_runtime.h>
#include <cuda_fp16.h>
#include <math.h>
#include <stdint.h>

#define BATCH   4
#define SEQ     4096
#define EMB     1024
#define HEADS   16
#define HD      64
#define DFF     4096
#define WIN     128
#define NB      (SEQ / WIN)
#define M_TOK   (BATCH * SEQ)

/* ---------------- scratch ---------------- */
__device__ __half g_xnh[(size_t)M_TOK * EMB];
__device__ float  g_qkv[(size_t)M_TOK * 3 * EMB];
__device__ __half g_attnh[(size_t)M_TOK * EMB];
__device__ __half g_hbufh[(size_t)M_TOK * DFF];
__device__ __half g_wqh[(size_t)3 * EMB * EMB];
__device__ __half g_wph[(size_t)EMB * EMB];
__device__ __half g_w1h[(size_t)DFF * EMB];
__device__ __half g_w2h[(size_t)EMB * DFF];

/* ---------------- PTX helpers ---------------- */
__device__ __forceinline__ uint32_t smem_u32(const void* p)
{
    uint32_t a;
    asm("{ .reg .u64 t; cvta.to.shared.u64 t, %1; cvt.u32.u64 %0, t; }" : "=r"(a) : "l"(p));
    return a;
}
__device__ __forceinline__ void cp16(uint32_t s, const void* g)
{
    asm volatile("cp.async.cg.shared.global [%0], [%1], 16;" :: "r"(s), "l"(g));
}
__device__ __forceinline__ void cp_commit() { asm volatile("cp.async.commit_group;"); }
template<int N>
__device__ __forceinline__ void cp_wait() { asm volatile("cp.async.wait_group %0;" :: "n"(N)); }

__device__ __forceinline__ void ldsm_x4(uint32_t* r, uint32_t addr)
{
    asm volatile("ldmatrix.sync.aligned.m8n8.x4.shared.b16 {%0,%1,%2,%3}, [%4];"
                 : "=r"(r[0]), "=r"(r[1]), "=r"(r[2]), "=r"(r[3]) : "r"(addr));
}
__device__ __forceinline__ void mma_f16(float* d, const uint32_t* a, const uint32_t* b)
{
    asm volatile(
        "mma.sync.aligned.m16n8k16.row.col.f32.f16.f16.f32 "
        "{%0,%1,%2,%3},{%4,%5,%6,%7},{%8,%9},{%0,%1,%2,%3};"
        : "+f"(d[0]), "+f"(d[1]), "+f"(d[2]), "+f"(d[3])
        : "r"(a[0]), "r"(a[1]), "r"(a[2]), "r"(a[3]), "r"(b[0]), "r"(b[1]));
}

/* ---------------- fp16 tensor-core GEMM ----------------
 * C[M,N] = A[M,K] @ B[N,K]^T + bias (+epilogue); half in, fp32 accum.
 * CTA tile 128x256, BK=32, 256 thr / 8 warps (warp tile 64x64),
 * 3-stage cp.async ring, ldmatrix.x4 fragments, pad-40 smem rows. */
#define BM 128
#define BN 256
#define BKD 32
#define ROWP 40                               /* padded halves per row   */
#define A_STG (BM * ROWP * 2)                 /* 10240 B */
#define B_STG (BN * ROWP * 2)                 /* 20480 B */
#define HSMEM (3 * (A_STG + B_STG))           /* 92160 B */

#define EPI_NONE 0
#define EPI_ADD  1
#define EPI_GELU 2

template<int EPI, int OUTH>
__global__ __launch_bounds__(256, 1)
void hgemm(const __half* __restrict__ A, const __half* __restrict__ B,
           const float* __restrict__ bias, const float* __restrict__ R,
           void* __restrict__ Cv, int M, int N, int K)
{
    extern __shared__ __align__(16) uint8_t dyn[];
    const uint32_t smem0 = smem_u32(dyn);
    const uint32_t aBase = smem0;
    const uint32_t bBase = smem0 + 3 * A_STG;

    const int tid = threadIdx.x;
    const int wid = tid >> 5;
    const int lane = tid & 31;
    const int g = lane >> 2;
    const int tg = lane & 3;
    const int bm = blockIdx.y * BM;
    const int bn = blockIdx.x * BN;
    const int warp_m = (wid & 1) * 64;
    const int warp_n = (wid >> 1) * 64;

    /* staging map: chunk c -> row=c>>2, 16B seg = c&3 */
    const int srow = tid >> 2;                /* 0..63 */
    const int sseg = (tid & 3) * 8;           /* halves offset */

    /* ldmatrix lane addresses (bytes from stage base) */
    const uint32_t a_lane = (uint32_t)((warp_m + (lane & 15)) * ROWP + (lane >> 4) * 8) * 2;
    const uint32_t b_lane = (uint32_t)((warp_n + (lane & 7) + (lane >> 4) * 8) * ROWP
                                       + ((lane >> 3) & 1) * 8) * 2;

    float acc[4][8][4];
    #pragma unroll
    for (int i = 0; i < 4; i++)
        #pragma unroll
        for (int j = 0; j < 8; j++)
            #pragma unroll
            for (int r = 0; r < 4; r++) acc[i][j][r] = 0.f;

    auto load_stage = [&](int s) {
        const int st = s % 3;
        const int k0 = s * BKD;
        #pragma unroll
        for (int i = 0; i < 2; i++) {         /* A: 128 rows */
            const int row = srow + i * 64;
            cp16(aBase + st * A_STG + (uint32_t)(row * ROWP + sseg) * 2,
                 A + (size_t)(bm + row) * K + k0 + sseg);
        }
        #pragma unroll
        for (int i = 0; i < 4; i++) {         /* B: 256 rows */
            const int row = srow + i * 64;
            cp16(bBase + st * B_STG + (uint32_t)(row * ROWP + sseg) * 2,
                 B + (size_t)(bn + row) * K + k0 + sseg);
        }
        cp_commit();
    };

    const int S = K / BKD;
    load_stage(0);
    load_stage(1);

    for (int s = 0; s < S; s++) {
        if (s + 1 < S) cp_wait<1>(); else cp_wait<0>();
        __syncthreads();
        if (s + 2 < S) load_stage(s + 2);

        const int st = s % 3;
        const uint32_t aS = aBase + st * A_STG + a_lane;
        const uint32_t bS = bBase + st * B_STG + b_lane;

        #pragma unroll
        for (int ks = 0; ks < 2; ks++) {
            const uint32_t kc2 = ks * 32;     /* 16 halves = 32 bytes */
            uint32_t a[4][4], b[4][4];
            #pragma unroll
            for (int mt = 0; mt < 4; mt++)
                ldsm_x4(a[mt], aS + kc2 + mt * (16 * ROWP * 2));
            #pragma unroll
            for (int p = 0; p < 4; p++)
                ldsm_x4(b[p], bS + kc2 + p * (16 * ROWP * 2));
            #pragma unroll
            for (int mt = 0; mt < 4; mt++)
                #pragma unroll
                for (int nt = 0; nt < 8; nt++)
                    mma_f16(acc[mt][nt], a[mt], &b[nt >> 1][(nt & 1) * 2]);
        }
    }

    /* epilogue */
    #pragma unroll
    for (int mt = 0; mt < 4; mt++) {
        #pragma unroll
        for (int h = 0; h < 2; h++) {
            const int row = bm + warp_m + mt * 16 + g + h * 8;
            #pragma unroll
            for (int nt = 0; nt < 8; nt++) {
                const int col = bn + warp_n + nt * 8 + tg * 2;
                float c0 = acc[mt][nt][h * 2 + 0];
                float c1 = acc[mt][nt][h * 2 + 1];
                const float2 bv = *(const float2*)(bias + col);
                c0 += bv.x; c1 += bv.y;
                if (EPI == EPI_ADD) {
                    const float2 rv = *(const float2*)(R + (size_t)row * N + col);
                    c0 += rv.x; c1 += rv.y;
                }
                if (EPI == EPI_GELU) {
                    c0 = 0.5f * c0 * (1.f + erff(c0 * 0.70710678118654752f));
                    c1 = 0.5f * c1 * (1.f + erff(c1 * 0.70710678118654752f));
                }
                if (OUTH) {
                    ((__half2*)Cv)[((size_t)row * N + col) >> 1] = __floats2half2_rn(c0, c1);
                } else {
                    float2 o; o.x = c0; o.y = c1;
                    *(float2*)((float*)Cv + (size_t)row * N + col) = o;
                }
            }
        }
    }
}

/* ---------------- weight fp32 -> half ---------------- */
__global__ __launch_bounds__(256)
void w2h_kernel(const float* __restrict__ src, __half* __restrict__ dst, int n4)
{
    const int i = blockIdx.x * 256 + threadIdx.x;
    if (i < n4) {
        float4 v = ((const float4*)src)[i];
        __half2* d = (__half2*)(dst + (size_t)i * 4);
        d[0] = __floats2half2_rn(v.x, v.y);
        d[1] = __floats2half2_rn(v.z, v.w);
    }
}

/* ---------------- block reduction ---------------- */
__device__ __forceinline__ float block_sum_1024(float v, float* sh)
{
    #pragma unroll
    for (int o = 16; o > 0; o >>= 1)
        v += __shfl_xor_sync(0xFFFFFFFFu, v, o);
    const int wid = threadIdx.x >> 5;
    const int lane = threadIdx.x & 31;
    if (lane == 0) sh[wid] = v;
    __syncthreads();
    if (wid == 0) {
        float t = (lane < 8) ? sh[lane] : 0.f;
        #pragma unroll
        for (int o = 4; o > 0; o >>= 1)
            t += __shfl_xor_sync(0xFFFFFFFFu, t, o);
        if (lane == 0) sh[8] = t;
    }
    __syncthreads();
    float r = sh[8];
    __syncthreads();
    return r;
}

/* ---------------- LayerNorm -> half ---------------- */
__global__ __launch_bounds__(256)
void ln_kernel(const float* __restrict__ x, const float* __restrict__ w,
               const float* __restrict__ b, __half* __restrict__ out)
{
    __shared__ float sh[9];
    const int row = blockIdx.x;
    const int t = threadIdx.x;
    const float* xr = x + (size_t)row * EMB;

    float4 v = *(const float4*)(xr + t * 4);
    float mu = block_sum_1024(v.x + v.y + v.z + v.w, sh) * (1.f / EMB);

    float d0 = v.x - mu, d1 = v.y - mu, d2 = v.z - mu, d3 = v.w - mu;
    float var = block_sum_1024(d0 * d0 + d1 * d1 + d2 * d2 + d3 * d3, sh) * (1.f / EMB);
    float rs = rsqrtf(var + 1e-5f);

    float4 wv = *(const float4*)(w + t * 4);
    float4 bv = *(const float4*)(b + t * 4);
    __half2* orow = (__half2*)(out + (size_t)row * EMB + t * 4);
    orow[0] = __floats2half2_rn(d0 * rs * wv.x + bv.x, d1 * rs * wv.y + bv.y);
    orow[1] = __floats2half2_rn(d2 * rs * wv.z + bv.z, d3 * rs * wv.w + bv.w);
}

/* ---------------- local windowed attention ---------------- */
__global__ __launch_bounds__(128)
void lattn_kernel(const float* __restrict__ qkv, __half* __restrict__ out)
{
    __shared__ float ks[64][64];
    __shared__ float vs[64][64];

    const int bi = blockIdx.x;
    const int bh = blockIdx.y;
    const int b = bh >> 4, h = bh & 15;
    const int tid = threadIdx.x;
    const int pos = bi * WIN + tid;

    const float* base = qkv + (size_t)b * SEQ * (3 * EMB);

    float q[HD];
    {
        const float* qr = base + (size_t)pos * (3 * EMB) + h * HD;
        #pragma unroll
        for (int d = 0; d < HD; d += 4) {
            float4 t = *(const float4*)(qr + d);
            q[d + 0] = t.x * 0.125f; q[d + 1] = t.y * 0.125f;
            q[d + 2] = t.z * 0.125f; q[d + 3] = t.w * 0.125f;
        }
    }

    float m = -INFINITY, l = 0.f;
    float acc[HD];
    #pragma unroll
    for (int d = 0; d < HD; d++) acc[d] = 0.f;

    const int lrow = tid >> 1;
    const int lcol = (tid & 1) * 32;

    for (int sb = bi - 1; sb <= bi + 1; sb++) {
        if (sb < 0 || sb >= NB) continue;
        for (int half = 0; half < 2; half++) {
            const int krow0 = sb * WIN + half * 64;
            __syncthreads();
            {
                const float* kr = base + (size_t)(krow0 + lrow) * (3 * EMB) + EMB     + h * HD + lcol;
                const float* vr = base + (size_t)(krow0 + lrow) * (3 * EMB) + 2 * EMB + h * HD + lcol;
                #pragma unroll
                for (int i = 0; i < 32; i += 4) {
                    *(float4*)&ks[lrow][lcol + i] = *(const float4*)(kr + i);
                    *(float4*)&vs[lrow][lcol + i] = *(const float4*)(vr + i);
                }
            }
            __syncthreads();

            #pragma unroll
            for (int c0 = 0; c0 < 64; c0 += 32) {
                float s[32];
                float cmax = -INFINITY;
                #pragma unroll 8
                for (int j = 0; j < 32; j++) {
                    float t = 0.f;
                    #pragma unroll
                    for (int d = 0; d < HD; d += 4) {
                        float4 kv = *(const float4*)&ks[c0 + j][d];
                        t += q[d] * kv.x + q[d + 1] * kv.y + q[d + 2] * kv.z + q[d + 3] * kv.w;
                    }
                    s[j] = t;
                    cmax = fmaxf(cmax, t);
                }
                const float mn = fmaxf(m, cmax);
                const float corr = __expf(m - mn);
                l *= corr;
                #pragma unroll
                for (int d = 0; d < HD; d++) acc[d] *= corr;
                #pragma unroll 8
                for (int j = 0; j < 32; j++) {
                    const float p = __expf(s[j] - mn);
                    l += p;
                    #pragma unroll
                    for (int d = 0; d < HD; d += 4) {
                        float4 vv = *(const float4*)&vs[c0 + j][d];
                        acc[d + 0] += p * vv.x;
                        acc[d + 1] += p * vv.y;
                        acc[d + 2] += p * vv.z;
                        acc[d + 3] += p * vv.w;
                    }
                }
                m = mn;
            }
        }
    }

    const float inv = 1.f / l;
    __half2* orow = (__half2*)(out + (size_t)(b * SEQ + pos) * EMB + h * HD);
    #pragma unroll
    for (int d = 0; d < HD; d += 2)
        orow[d >> 1] = __floats2half2_rn(acc[d] * inv, acc[d + 1] * inv);
}

/* ---------------- launch ---------------- */
extern "C" void kernel_launch(void* const* d_in, const int* in_sizes, int n_in,
                              void* d_out, int out_size)
{
    const float* x     = (const float*)d_in[0];
    const float* ln1w  = (const float*)d_in[1];
    const float* ln1b  = (const float*)d_in[2];
    const float* qkvw  = (const float*)d_in[3];
    const float* qkvb  = (const float*)d_in[4];
    const float* projw = (const float*)d_in[5];
    const float* projb = (const float*)d_in[6];
    const float* ln2w  = (const float*)d_in[7];
    const float* ln2b  = (const float*)d_in[8];
    const float* fc1w  = (const float*)d_in[9];
    const float* fc1b  = (const float*)d_in[10];
    const float* fc2w  = (const float*)d_in[11];
    const float* fc2b  = (const float*)d_in[12];
    float* out = (float*)d_out;

    __half *xnh, *attnh, *hbufh, *wqh, *wph, *w1h, *w2h;
    float *qkv;
    cudaGetSymbolAddress((void**)&xnh,   g_xnh);
    cudaGetSymbolAddress((void**)&qkv,   g_qkv);
    cudaGetSymbolAddress((void**)&attnh, g_attnh);
    cudaGetSymbolAddress((void**)&hbufh, g_hbufh);
    cudaGetSymbolAddress((void**)&wqh,   g_wqh);
    cudaGetSymbolAddress((void**)&wph,   g_wph);
    cudaGetSymbolAddress((void**)&w1h,   g_w1h);
    cudaGetSymbolAddress((void**)&w2h,   g_w2h);

    cudaFuncSetAttribute(hgemm<EPI_NONE, 0>, cudaFuncAttributeMaxDynamicSharedMemorySize, HSMEM);
    cudaFuncSetAttribute(hgemm<EPI_ADD, 0>,  cudaFuncAttributeMaxDynamicSharedMemorySize, HSMEM);
    cudaFuncSetAttribute(hgemm<EPI_GELU, 1>, cudaFuncAttributeMaxDynamicSharedMemorySize, HSMEM);

    w2h_kernel<<<(3 * EMB * EMB / 4 + 255) / 256, 256>>>(qkvw, wqh, 3 * EMB * EMB / 4);
    w2h_kernel<<<(EMB * EMB / 4 + 255) / 256, 256>>>(projw, wph, EMB * EMB / 4);
    w2h_kernel<<<(DFF * EMB / 4 + 255) / 256, 256>>>(fc1w, w1h, DFF * EMB / 4);
    w2h_kernel<<<(EMB * DFF / 4 + 255) / 256, 256>>>(fc2w, w2h, EMB * DFF / 4);

    ln_kernel<<<M_TOK, 256>>>(x, ln1w, ln1b, xnh);
    hgemm<EPI_NONE, 0><<<dim3(3 * EMB / BN, M_TOK / BM), 256, HSMEM>>>(
        xnh, wqh, qkvb, nullptr, qkv, M_TOK, 3 * EMB, EMB);
    lattn_kernel<<<dim3(NB, BATCH * HEADS), 128>>>(qkv, attnh);
    hgemm<EPI_ADD, 0><<<dim3(EMB / BN, M_TOK / BM), 256, HSMEM>>>(
        attnh, wph, projb, x, out, M_TOK, EMB, EMB);
    ln_kernel<<<M_TOK, 256>>>(out, ln2w, ln2b, xnh);
    hgemm<EPI_GELU, 1><<<dim3(DFF / BN, M_TOK / BM), 256, HSMEM>>>(
        xnh, w1h, fc1b, nullptr, hbufh, M_TOK, DFF, EMB);
    hgemm<EPI_ADD, 0><<<dim3(EMB / BN, M_TOK / BM), 256, HSMEM>>>(
        hbufh, w2h, fc2b, out, out, M_TOK, EMB, DFF);
}

// round 13
// speedup vs baseline: 1.1540x; 1.1540x over previous
#include <cuda_runtime.h>
#include <cuda_fp16.h>
#include <math.h>
#include <stdint.h>

#define BATCH   4
#define SEQ     4096
#define EMB     1024
#define HEADS   16
#define HD      64
#define DFF     4096
#define WIN     128
#define NB      (SEQ / WIN)
#define M_TOK   (BATCH * SEQ)

/* ---------------- scratch ---------------- */
__device__ __half g_xnh[(size_t)M_TOK * EMB];
__device__ float  g_qkv[(size_t)M_TOK * 3 * EMB];
__device__ __half g_attnh[(size_t)M_TOK * EMB];
__device__ __half g_hbufh[(size_t)M_TOK * DFF];
__device__ __half g_wqh[(size_t)3 * EMB * EMB];
__device__ __half g_wph[(size_t)EMB * EMB];
__device__ __half g_w1h[(size_t)DFF * EMB];
__device__ __half g_w2h[(size_t)EMB * DFF];

/* ---------------- PTX helpers ---------------- */
__device__ __forceinline__ uint32_t smem_u32(const void* p)
{
    uint32_t a;
    asm("{ .reg .u64 t; cvta.to.shared.u64 t, %1; cvt.u32.u64 %0, t; }" : "=r"(a) : "l"(p));
    return a;
}
__device__ __forceinline__ void cp16(uint32_t s, const void* g)
{
    asm volatile("cp.async.cg.shared.global [%0], [%1], 16;" :: "r"(s), "l"(g));
}
__device__ __forceinline__ void cp_commit() { asm volatile("cp.async.commit_group;"); }
template<int N>
__device__ __forceinline__ void cp_wait() { asm volatile("cp.async.wait_group %0;" :: "n"(N)); }

__device__ __forceinline__ void ldsm_x4(uint32_t* r, uint32_t addr)
{
    asm volatile("ldmatrix.sync.aligned.m8n8.x4.shared.b16 {%0,%1,%2,%3}, [%4];"
                 : "=r"(r[0]), "=r"(r[1]), "=r"(r[2]), "=r"(r[3]) : "r"(addr));
}
__device__ __forceinline__ void mma_f16(float* d, const uint32_t* a, const uint32_t* b)
{
    asm volatile(
        "mma.sync.aligned.m16n8k16.row.col.f32.f16.f16.f32 "
        "{%0,%1,%2,%3},{%4,%5,%6,%7},{%8,%9},{%0,%1,%2,%3};"
        : "+f"(d[0]), "+f"(d[1]), "+f"(d[2]), "+f"(d[3])
        : "r"(a[0]), "r"(a[1]), "r"(a[2]), "r"(a[3]), "r"(b[0]), "r"(b[1]));
}

/* ---------------- fp16 tensor-core GEMM ----------------
 * C[M,N] = A[M,K] @ B[N,K]^T + bias (+epilogue); half in, fp32 accum.
 * CTA 128x128 (2 CTAs/SM), warp tile 64x32, BK=32,
 * 3-stage cp.async ring, single barrier/iter, ldmatrix.x4, pad-40 rows. */
#define BM 128
#define BN 128
#define BKD 32
#define ROWP 40                               /* padded halves per row */
#define T_STG (128 * ROWP * 2)                /* 10240 B per operand stage */
#define HSMEM (3 * 2 * T_STG)                 /* 61440 B */

#define EPI_NONE 0
#define EPI_ADD  1
#define EPI_GELU 2

template<int EPI, int OUTH>
__global__ __launch_bounds__(256, 2)
void hgemm(const __half* __restrict__ A, const __half* __restrict__ B,
           const float* __restrict__ bias, const float* __restrict__ R,
           void* __restrict__ Cv, int M, int N, int K)
{
    extern __shared__ __align__(16) uint8_t dyn[];
    const uint32_t smem0 = smem_u32(dyn);
    const uint32_t aBase = smem0;
    const uint32_t bBase = smem0 + 3 * T_STG;

    const int tid = threadIdx.x;
    const int wid = tid >> 5;
    const int lane = tid & 31;
    const int g = lane >> 2;
    const int tg = lane & 3;
    const int bm = blockIdx.y * BM;
    const int bn = blockIdx.x * BN;
    const int warp_m = (wid & 1) * 64;
    const int warp_n = (wid >> 1) * 32;

    /* staging map: chunk c -> row=c>>2, 16B seg = c&3 */
    const int srow = tid >> 2;                /* 0..63 */
    const int sseg = (tid & 3) * 8;           /* halves offset */

    /* ldmatrix lane addresses (bytes from stage base); verified in R11 */
    const uint32_t a_lane = (uint32_t)((warp_m + (lane & 15)) * ROWP + (lane >> 4) * 8) * 2;
    const uint32_t b_lane = (uint32_t)((warp_n + (lane & 7) + (lane >> 4) * 8) * ROWP
                                       + ((lane >> 3) & 1) * 8) * 2;

    float acc[4][4][4];
    #pragma unroll
    for (int i = 0; i < 4; i++)
        #pragma unroll
        for (int j = 0; j < 4; j++)
            #pragma unroll
            for (int r = 0; r < 4; r++) acc[i][j][r] = 0.f;

    auto load_stage = [&](int s) {
        const int st = s % 3;
        const int k0 = s * BKD;
        #pragma unroll
        for (int i = 0; i < 2; i++) {
            const int row = srow + i * 64;
            cp16(aBase + st * T_STG + (uint32_t)(row * ROWP + sseg) * 2,
                 A + (size_t)(bm + row) * K + k0 + sseg);
            cp16(bBase + st * T_STG + (uint32_t)(row * ROWP + sseg) * 2,
                 B + (size_t)(bn + row) * K + k0 + sseg);
        }
        cp_commit();
    };

    const int S = K / BKD;
    load_stage(0);
    load_stage(1);

    for (int s = 0; s < S; s++) {
        if (s + 1 < S) cp_wait<1>(); else cp_wait<0>();
        __syncthreads();
        if (s + 2 < S) load_stage(s + 2);

        const int st = s % 3;
        const uint32_t aS = aBase + st * T_STG + a_lane;
        const uint32_t bS = bBase + st * T_STG + b_lane;

        #pragma unroll
        for (int ks = 0; ks < 2; ks++) {
            const uint32_t kc2 = ks * 32;     /* 16 halves = 32 bytes */
            uint32_t a[4][4], b[2][4];
            #pragma unroll
            for (int mt = 0; mt < 4; mt++)
                ldsm_x4(a[mt], aS + kc2 + mt * (16 * ROWP * 2));
            #pragma unroll
            for (int p = 0; p < 2; p++)
                ldsm_x4(b[p], bS + kc2 + p * (16 * ROWP * 2));
            #pragma unroll
            for (int mt = 0; mt < 4; mt++)
                #pragma unroll
                for (int nt = 0; nt < 4; nt++)
                    mma_f16(acc[mt][nt], a[mt], &b[nt >> 1][(nt & 1) * 2]);
        }
    }

    /* epilogue */
    #pragma unroll
    for (int mt = 0; mt < 4; mt++) {
        #pragma unroll
        for (int h = 0; h < 2; h++) {
            const int row = bm + warp_m + mt * 16 + g + h * 8;
            #pragma unroll
            for (int nt = 0; nt < 4; nt++) {
                const int col = bn + warp_n + nt * 8 + tg * 2;
                float c0 = acc[mt][nt][h * 2 + 0];
                float c1 = acc[mt][nt][h * 2 + 1];
                const float2 bv = *(const float2*)(bias + col);
                c0 += bv.x; c1 += bv.y;
                if (EPI == EPI_ADD) {
                    const float2 rv = *(const float2*)(R + (size_t)row * N + col);
                    c0 += rv.x; c1 += rv.y;
                }
                if (EPI == EPI_GELU) {
                    c0 = 0.5f * c0 * (1.f + erff(c0 * 0.70710678118654752f));
                    c1 = 0.5f * c1 * (1.f + erff(c1 * 0.70710678118654752f));
                }
                if (OUTH) {
                    ((__half2*)Cv)[((size_t)row * N + col) >> 1] = __floats2half2_rn(c0, c1);
                } else {
                    float2 o; o.x = c0; o.y = c1;
                    *(float2*)((float*)Cv + (size_t)row * N + col) = o;
                }
            }
        }
    }
}

/* ---------------- weight fp32 -> half ---------------- */
__global__ __launch_bounds__(256)
void w2h_kernel(const float* __restrict__ src, __half* __restrict__ dst, int n4)
{
    const int i = blockIdx.x * 256 + threadIdx.x;
    if (i < n4) {
        float4 v = ((const float4*)src)[i];
        __half2* d = (__half2*)(dst + (size_t)i * 4);
        d[0] = __floats2half2_rn(v.x, v.y);
        d[1] = __floats2half2_rn(v.z, v.w);
    }
}

/* ---------------- block reduction ---------------- */
__device__ __forceinline__ float block_sum_1024(float v, float* sh)
{
    #pragma unroll
    for (int o = 16; o > 0; o >>= 1)
        v += __shfl_xor_sync(0xFFFFFFFFu, v, o);
    const int wid = threadIdx.x >> 5;
    const int lane = threadIdx.x & 31;
    if (lane == 0) sh[wid] = v;
    __syncthreads();
    if (wid == 0) {
        float t = (lane < 8) ? sh[lane] : 0.f;
        #pragma unroll
        for (int o = 4; o > 0; o >>= 1)
            t += __shfl_xor_sync(0xFFFFFFFFu, t, o);
        if (lane == 0) sh[8] = t;
    }
    __syncthreads();
    float r = sh[8];
    __syncthreads();
    return r;
}

/* ---------------- LayerNorm -> half ---------------- */
__global__ __launch_bounds__(256)
void ln_kernel(const float* __restrict__ x, const float* __restrict__ w,
               const float* __restrict__ b, __half* __restrict__ out)
{
    __shared__ float sh[9];
    const int row = blockIdx.x;
    const int t = threadIdx.x;
    const float* xr = x + (size_t)row * EMB;

    float4 v = *(const float4*)(xr + t * 4);
    float mu = block_sum_1024(v.x + v.y + v.z + v.w, sh) * (1.f / EMB);

    float d0 = v.x - mu, d1 = v.y - mu, d2 = v.z - mu, d3 = v.w - mu;
    float var = block_sum_1024(d0 * d0 + d1 * d1 + d2 * d2 + d3 * d3, sh) * (1.f / EMB);
    float rs = rsqrtf(var + 1e-5f);

    float4 wv = *(const float4*)(w + t * 4);
    float4 bv = *(const float4*)(b + t * 4);
    __half2* orow = (__half2*)(out + (size_t)row * EMB + t * 4);
    orow[0] = __floats2half2_rn(d0 * rs * wv.x + bv.x, d1 * rs * wv.y + bv.y);
    orow[1] = __floats2half2_rn(d2 * rs * wv.z + bv.z, d3 * rs * wv.w + bv.w);
}

/* ---------------- local windowed attention ---------------- */
__global__ __launch_bounds__(128)
void lattn_kernel(const float* __restrict__ qkv, __half* __restrict__ out)
{
    __shared__ float ks[64][64];
    __shared__ float vs[64][64];

    const int bi = blockIdx.x;
    const int bh = blockIdx.y;
    const int b = bh >> 4, h = bh & 15;
    const int tid = threadIdx.x;
    const int pos = bi * WIN + tid;

    const float* base = qkv + (size_t)b * SEQ * (3 * EMB);

    float q[HD];
    {
        const float* qr = base + (size_t)pos * (3 * EMB) + h * HD;
        #pragma unroll
        for (int d = 0; d < HD; d += 4) {
            float4 t = *(const float4*)(qr + d);
            q[d + 0] = t.x * 0.125f; q[d + 1] = t.y * 0.125f;
            q[d + 2] = t.z * 0.125f; q[d + 3] = t.w * 0.125f;
        }
    }

    float m = -INFINITY, l = 0.f;
    float acc[HD];
    #pragma unroll
    for (int d = 0; d < HD; d++) acc[d] = 0.f;

    const int lrow = tid >> 1;
    const int lcol = (tid & 1) * 32;

    for (int sb = bi - 1; sb <= bi + 1; sb++) {
        if (sb < 0 || sb >= NB) continue;
        for (int half = 0; half < 2; half++) {
            const int krow0 = sb * WIN + half * 64;
            __syncthreads();
            {
                const float* kr = base + (size_t)(krow0 + lrow) * (3 * EMB) + EMB     + h * HD + lcol;
                const float* vr = base + (size_t)(krow0 + lrow) * (3 * EMB) + 2 * EMB + h * HD + lcol;
                #pragma unroll
                for (int i = 0; i < 32; i += 4) {
                    *(float4*)&ks[lrow][lcol + i] = *(const float4*)(kr + i);
                    *(float4*)&vs[lrow][lcol + i] = *(const float4*)(vr + i);
                }
            }
            __syncthreads();

            #pragma unroll
            for (int c0 = 0; c0 < 64; c0 += 32) {
                float s[32];
                float cmax = -INFINITY;
                #pragma unroll 8
                for (int j = 0; j < 32; j++) {
                    float t = 0.f;
                    #pragma unroll
                    for (int d = 0; d < HD; d += 4) {
                        float4 kv = *(const float4*)&ks[c0 + j][d];
                        t += q[d] * kv.x + q[d + 1] * kv.y + q[d + 2] * kv.z + q[d + 3] * kv.w;
                    }
                    s[j] = t;
                    cmax = fmaxf(cmax, t);
                }
                const float mn = fmaxf(m, cmax);
                const float corr = __expf(m - mn);
                l *= corr;
                #pragma unroll
                for (int d = 0; d < HD; d++) acc[d] *= corr;
                #pragma unroll 8
                for (int j = 0; j < 32; j++) {
                    const float p = __expf(s[j] - mn);
                    l += p;
                    #pragma unroll
                    for (int d = 0; d < HD; d += 4) {
                        float4 vv = *(const float4*)&vs[c0 + j][d];
                        acc[d + 0] += p * vv.x;
                        acc[d + 1] += p * vv.y;
                        acc[d + 2] += p * vv.z;
                        acc[d + 3] += p * vv.w;
                    }
                }
                m = mn;
            }
        }
    }

    const float inv = 1.f / l;
    __half2* orow = (__half2*)(out + (size_t)(b * SEQ + pos) * EMB + h * HD);
    #pragma unroll
    for (int d = 0; d < HD; d += 2)
        orow[d >> 1] = __floats2half2_rn(acc[d] * inv, acc[d + 1] * inv);
}

/* ---------------- launch ---------------- */
extern "C" void kernel_launch(void* const* d_in, const int* in_sizes, int n_in,
                              void* d_out, int out_size)
{
    const float* x     = (const float*)d_in[0];
    const float* ln1w  = (const float*)d_in[1];
    const float* ln1b  = (const float*)d_in[2];
    const float* qkvw  = (const float*)d_in[3];
    const float* qkvb  = (const float*)d_in[4];
    const float* projw = (const float*)d_in[5];
    const float* projb = (const float*)d_in[6];
    const float* ln2w  = (const float*)d_in[7];
    const float* ln2b  = (const float*)d_in[8];
    const float* fc1w  = (const float*)d_in[9];
    const float* fc1b  = (const float*)d_in[10];
    const float* fc2w  = (const float*)d_in[11];
    const float* fc2b  = (const float*)d_in[12];
    float* out = (float*)d_out;

    __half *xnh, *attnh, *hbufh, *wqh, *wph, *w1h, *w2h;
    float *qkv;
    cudaGetSymbolAddress((void**)&xnh,   g_xnh);
    cudaGetSymbolAddress((void**)&qkv,   g_qkv);
    cudaGetSymbolAddress((void**)&attnh, g_attnh);
    cudaGetSymbolAddress((void**)&hbufh, g_hbufh);
    cudaGetSymbolAddress((void**)&wqh,   g_wqh);
    cudaGetSymbolAddress((void**)&wph,   g_wph);
    cudaGetSymbolAddress((void**)&w1h,   g_w1h);
    cudaGetSymbolAddress((void**)&w2h,   g_w2h);

    cudaFuncSetAttribute(hgemm<EPI_NONE, 0>, cudaFuncAttributeMaxDynamicSharedMemorySize, HSMEM);
    cudaFuncSetAttribute(hgemm<EPI_ADD, 0>,  cudaFuncAttributeMaxDynamicSharedMemorySize, HSMEM);
    cudaFuncSetAttribute(hgemm<EPI_GELU, 1>, cudaFuncAttributeMaxDynamicSharedMemorySize, HSMEM);

    w2h_kernel<<<(3 * EMB * EMB / 4 + 255) / 256, 256>>>(qkvw, wqh, 3 * EMB * EMB / 4);
    w2h_kernel<<<(EMB * EMB / 4 + 255) / 256, 256>>>(projw, wph, EMB * EMB / 4);
    w2h_kernel<<<(DFF * EMB / 4 + 255) / 256, 256>>>(fc1w, w1h, DFF * EMB / 4);
    w2h_kernel<<<(EMB * DFF / 4 + 255) / 256, 256>>>(fc2w, w2h, EMB * DFF / 4);

    ln_kernel<<<M_TOK, 256>>>(x, ln1w, ln1b, xnh);
    hgemm<EPI_NONE, 0><<<dim3(3 * EMB / BN, M_TOK / BM), 256, HSMEM>>>(
        xnh, wqh, qkvb, nullptr, qkv, M_TOK, 3 * EMB, EMB);
    lattn_kernel<<<dim3(NB, BATCH * HEADS), 128>>>(qkv, attnh);
    hgemm<EPI_ADD, 0><<<dim3(EMB / BN, M_TOK / BM), 256, HSMEM>>>(
        attnh, wph, projb, x, out, M_TOK, EMB, EMB);
    ln_kernel<<<M_TOK, 256>>>(out, ln2w, ln2b, xnh);
    hgemm<EPI_GELU, 1><<<dim3(DFF / BN, M_TOK / BM), 256, HSMEM>>>(
        xnh, w1h, fc1b, nullptr, hbufh, M_TOK, DFF, EMB);
    hgemm<EPI_ADD, 0><<<dim3(EMB / BN, M_TOK / BM), 256, HSMEM>>>(
        hbufh, w2h, fc2b, out, out, M_TOK, EMB, DFF);
}

// round 14
// speedup vs baseline: 1.7567x; 1.5223x over previous
#include <cuda_runtime.h>
#include <cuda_fp16.h>
#include <math.h>
#include <stdint.h>

#define BATCH   4
#define SEQ     4096
#define EMB     1024
#define HEADS   16
#define HD      64
#define DFF     4096
#define WIN     128
#define NB      (SEQ / WIN)
#define M_TOK   (BATCH * SEQ)

/* ---------------- scratch ---------------- */
__device__ __half g_xnh[(size_t)M_TOK * EMB];
__device__ float  g_qkv[(size_t)M_TOK * 3 * EMB];
__device__ __half g_attnh[(size_t)M_TOK * EMB];
__device__ __half g_hbufh[(size_t)M_TOK * DFF];
__device__ __half g_wqh[(size_t)3 * EMB * EMB];
__device__ __half g_wph[(size_t)EMB * EMB];
__device__ __half g_w1h[(size_t)DFF * EMB];
__device__ __half g_w2h[(size_t)EMB * DFF];

/* ---------------- PTX helpers ---------------- */
__device__ __forceinline__ uint32_t smem_u32(const void* p)
{
    uint32_t a;
    asm("{ .reg .u64 t; cvta.to.shared.u64 t, %1; cvt.u32.u64 %0, t; }" : "=r"(a) : "l"(p));
    return a;
}
__device__ __forceinline__ void cp16(uint32_t s, const void* g)
{
    asm volatile("cp.async.cg.shared.global [%0], [%1], 16;" :: "r"(s), "l"(g));
}
__device__ __forceinline__ void cp_commit() { asm volatile("cp.async.commit_group;"); }
template<int N>
__device__ __forceinline__ void cp_wait() { asm volatile("cp.async.wait_group %0;" :: "n"(N)); }

__device__ __forceinline__ void ldsm_x4(uint32_t* r, uint32_t addr)
{
    asm volatile("ldmatrix.sync.aligned.m8n8.x4.shared.b16 {%0,%1,%2,%3}, [%4];"
                 : "=r"(r[0]), "=r"(r[1]), "=r"(r[2]), "=r"(r[3]) : "r"(addr));
}
__device__ __forceinline__ void ldsm_x4_t(uint32_t* r, uint32_t addr)
{
    asm volatile("ldmatrix.sync.aligned.m8n8.x4.trans.shared.b16 {%0,%1,%2,%3}, [%4];"
                 : "=r"(r[0]), "=r"(r[1]), "=r"(r[2]), "=r"(r[3]) : "r"(addr));
}
__device__ __forceinline__ void mma_f16(float* d, const uint32_t* a, const uint32_t* b)
{
    asm volatile(
        "mma.sync.aligned.m16n8k16.row.col.f32.f16.f16.f32 "
        "{%0,%1,%2,%3},{%4,%5,%6,%7},{%8,%9},{%0,%1,%2,%3};"
        : "+f"(d[0]), "+f"(d[1]), "+f"(d[2]), "+f"(d[3])
        : "r"(a[0]), "r"(a[1]), "r"(a[2]), "r"(a[3]), "r"(b[0]), "r"(b[1]));
}

/* ---------------- fp16 tensor-core GEMM (round-13 winner, unchanged) -------- */
#define BM 128
#define BN 128
#define BKD 32
#define ROWP 40
#define T_STG (128 * ROWP * 2)
#define HSMEM (3 * 2 * T_STG)

#define EPI_NONE 0
#define EPI_ADD  1
#define EPI_GELU 2

template<int EPI, int OUTH>
__global__ __launch_bounds__(256, 2)
void hgemm(const __half* __restrict__ A, const __half* __restrict__ B,
           const float* __restrict__ bias, const float* __restrict__ R,
           void* __restrict__ Cv, int M, int N, int K)
{
    extern __shared__ __align__(16) uint8_t dyn[];
    const uint32_t smem0 = smem_u32(dyn);
    const uint32_t aBase = smem0;
    const uint32_t bBase = smem0 + 3 * T_STG;

    const int tid = threadIdx.x;
    const int wid = tid >> 5;
    const int lane = tid & 31;
    const int g = lane >> 2;
    const int tg = lane & 3;
    const int bm = blockIdx.y * BM;
    const int bn = blockIdx.x * BN;
    const int warp_m = (wid & 1) * 64;
    const int warp_n = (wid >> 1) * 32;

    const int srow = tid >> 2;
    const int sseg = (tid & 3) * 8;

    const uint32_t a_lane = (uint32_t)((warp_m + (lane & 15)) * ROWP + (lane >> 4) * 8) * 2;
    const uint32_t b_lane = (uint32_t)((warp_n + (lane & 7) + (lane >> 4) * 8) * ROWP
                                       + ((lane >> 3) & 1) * 8) * 2;

    float acc[4][4][4];
    #pragma unroll
    for (int i = 0; i < 4; i++)
        #pragma unroll
        for (int j = 0; j < 4; j++)
            #pragma unroll
            for (int r = 0; r < 4; r++) acc[i][j][r] = 0.f;

    auto load_stage = [&](int s) {
        const int st = s % 3;
        const int k0 = s * BKD;
        #pragma unroll
        for (int i = 0; i < 2; i++) {
            const int row = srow + i * 64;
            cp16(aBase + st * T_STG + (uint32_t)(row * ROWP + sseg) * 2,
                 A + (size_t)(bm + row) * K + k0 + sseg);
            cp16(bBase + st * T_STG + (uint32_t)(row * ROWP + sseg) * 2,
                 B + (size_t)(bn + row) * K + k0 + sseg);
        }
        cp_commit();
    };

    const int S = K / BKD;
    load_stage(0);
    load_stage(1);

    for (int s = 0; s < S; s++) {
        if (s + 1 < S) cp_wait<1>(); else cp_wait<0>();
        __syncthreads();
        if (s + 2 < S) load_stage(s + 2);

        const int st = s % 3;
        const uint32_t aS = aBase + st * T_STG + a_lane;
        const uint32_t bS = bBase + st * T_STG + b_lane;

        #pragma unroll
        for (int ks = 0; ks < 2; ks++) {
            const uint32_t kc2 = ks * 32;
            uint32_t a[4][4], b[2][4];
            #pragma unroll
            for (int mt = 0; mt < 4; mt++)
                ldsm_x4(a[mt], aS + kc2 + mt * (16 * ROWP * 2));
            #pragma unroll
            for (int p = 0; p < 2; p++)
                ldsm_x4(b[p], bS + kc2 + p * (16 * ROWP * 2));
            #pragma unroll
            for (int mt = 0; mt < 4; mt++)
                #pragma unroll
                for (int nt = 0; nt < 4; nt++)
                    mma_f16(acc[mt][nt], a[mt], &b[nt >> 1][(nt & 1) * 2]);
        }
    }

    #pragma unroll
    for (int mt = 0; mt < 4; mt++) {
        #pragma unroll
        for (int h = 0; h < 2; h++) {
            const int row = bm + warp_m + mt * 16 + g + h * 8;
            #pragma unroll
            for (int nt = 0; nt < 4; nt++) {
                const int col = bn + warp_n + nt * 8 + tg * 2;
                float c0 = acc[mt][nt][h * 2 + 0];
                float c1 = acc[mt][nt][h * 2 + 1];
                const float2 bv = *(const float2*)(bias + col);
                c0 += bv.x; c1 += bv.y;
                if (EPI == EPI_ADD) {
                    const float2 rv = *(const float2*)(R + (size_t)row * N + col);
                    c0 += rv.x; c1 += rv.y;
                }
                if (EPI == EPI_GELU) {
                    c0 = 0.5f * c0 * (1.f + erff(c0 * 0.70710678118654752f));
                    c1 = 0.5f * c1 * (1.f + erff(c1 * 0.70710678118654752f));
                }
                if (OUTH) {
                    ((__half2*)Cv)[((size_t)row * N + col) >> 1] = __floats2half2_rn(c0, c1);
                } else {
                    float2 o; o.x = c0; o.y = c1;
                    *(float2*)((float*)Cv + (size_t)row * N + col) = o;
                }
            }
        }
    }
}

/* ---------------- weight fp32 -> half ---------------- */
__global__ __launch_bounds__(256)
void w2h_kernel(const float* __restrict__ src, __half* __restrict__ dst, int n4)
{
    const int i = blockIdx.x * 256 + threadIdx.x;
    if (i < n4) {
        float4 v = ((const float4*)src)[i];
        __half2* d = (__half2*)(dst + (size_t)i * 4);
        d[0] = __floats2half2_rn(v.x, v.y);
        d[1] = __floats2half2_rn(v.z, v.w);
    }
}

/* ---------------- block reduction ---------------- */
__device__ __forceinline__ float block_sum_1024(float v, float* sh)
{
    #pragma unroll
    for (int o = 16; o > 0; o >>= 1)
        v += __shfl_xor_sync(0xFFFFFFFFu, v, o);
    const int wid = threadIdx.x >> 5;
    const int lane = threadIdx.x & 31;
    if (lane == 0) sh[wid] = v;
    __syncthreads();
    if (wid == 0) {
        float t = (lane < 8) ? sh[lane] : 0.f;
        #pragma unroll
        for (int o = 4; o > 0; o >>= 1)
            t += __shfl_xor_sync(0xFFFFFFFFu, t, o);
        if (lane == 0) sh[8] = t;
    }
    __syncthreads();
    float r = sh[8];
    __syncthreads();
    return r;
}

/* ---------------- LayerNorm -> half ---------------- */
__global__ __launch_bounds__(256)
void ln_kernel(const float* __restrict__ x, const float* __restrict__ w,
               const float* __restrict__ b, __half* __restrict__ out)
{
    __shared__ float sh[9];
    const int row = blockIdx.x;
    const int t = threadIdx.x;
    const float* xr = x + (size_t)row * EMB;

    float4 v = *(const float4*)(xr + t * 4);
    float mu = block_sum_1024(v.x + v.y + v.z + v.w, sh) * (1.f / EMB);

    float d0 = v.x - mu, d1 = v.y - mu, d2 = v.z - mu, d3 = v.w - mu;
    float var = block_sum_1024(d0 * d0 + d1 * d1 + d2 * d2 + d3 * d3, sh) * (1.f / EMB);
    float rs = rsqrtf(var + 1e-5f);

    float4 wv = *(const float4*)(w + t * 4);
    float4 bv = *(const float4*)(b + t * 4);
    __half2* orow = (__half2*)(out + (size_t)row * EMB + t * 4);
    orow[0] = __floats2half2_rn(d0 * rs * wv.x + bv.x, d1 * rs * wv.y + bv.y);
    orow[1] = __floats2half2_rn(d2 * rs * wv.z + bv.z, d3 * rs * wv.w + bv.w);
}

/* ---------------- tensorized local attention (flash-attn-2 style) ---------- */
#define AROWP 72
#define ASM_Q 0
#define ASM_K (128 * AROWP)
#define ASM_V (256 * AROWP)
#define ASMEM (3 * 128 * AROWP * 2)   /* 55296 B */

__global__ __launch_bounds__(256, 1)
void lattn_mma(const float* __restrict__ qkv, __half* __restrict__ out)
{
    extern __shared__ __align__(16) __half sm[];
    const uint32_t smb = smem_u32(sm);

    const int bi = blockIdx.x;
    const int bh = blockIdx.y;
    const int b = bh >> 4, h = bh & 15;
    const int tid = threadIdx.x;
    const int wid = tid >> 5;
    const int lane = tid & 31;
    const int g = lane >> 2;
    const int tg = lane & 3;

    const float* base = qkv + (size_t)b * SEQ * (3 * EMB);
    const int srow = tid >> 1;
    const int scol = (tid & 1) * 32;

    /* stage Q (scaled 0.125, half) */
    {
        const float* qr = base + (size_t)(bi * WIN + srow) * (3 * EMB) + h * HD + scol;
        __half2* dst = (__half2*)(sm + ASM_Q + srow * AROWP + scol);
        #pragma unroll
        for (int i = 0; i < 32; i += 8) {
            float4 v0 = *(const float4*)(qr + i);
            float4 v1 = *(const float4*)(qr + i + 4);
            dst[(i >> 1) + 0] = __floats2half2_rn(v0.x * 0.125f, v0.y * 0.125f);
            dst[(i >> 1) + 1] = __floats2half2_rn(v0.z * 0.125f, v0.w * 0.125f);
            dst[(i >> 1) + 2] = __floats2half2_rn(v1.x * 0.125f, v1.y * 0.125f);
            dst[(i >> 1) + 3] = __floats2half2_rn(v1.z * 0.125f, v1.w * 0.125f);
        }
    }
    __syncthreads();

    /* Q fragments: warp rows wid*16..+15, 4 ktiles */
    uint32_t qa[4][4];
    {
        const uint32_t al = smb + (uint32_t)((ASM_Q + (wid * 16 + (lane & 15)) * AROWP) * 2)
                          + (lane >> 4) * 16;
        #pragma unroll
        for (int kt = 0; kt < 4; kt++)
            ldsm_x4(qa[kt], al + kt * 32);
    }

    float m0 = -INFINITY, m1 = -INFINITY, l0 = 0.f, l1 = 0.f;
    float o[8][4];
    #pragma unroll
    for (int i = 0; i < 8; i++)
        #pragma unroll
        for (int r = 0; r < 4; r++) o[i][r] = 0.f;

    const int sb_lo = (bi > 0) ? bi - 1 : 0;
    const int sb_hi = (bi < NB - 1) ? bi + 1 : NB - 1;

    for (int sb = sb_lo; sb <= sb_hi; sb++) {
        __syncthreads();
        {
            const float* kr = base + (size_t)(sb * WIN + srow) * (3 * EMB) + EMB + h * HD + scol;
            const float* vr = kr + EMB;
            __half2* kd = (__half2*)(sm + ASM_K + srow * AROWP + scol);
            __half2* vd = (__half2*)(sm + ASM_V + srow * AROWP + scol);
            #pragma unroll
            for (int i = 0; i < 32; i += 8) {
                float4 a0 = *(const float4*)(kr + i);
                float4 a1 = *(const float4*)(kr + i + 4);
                kd[(i >> 1) + 0] = __floats2half2_rn(a0.x, a0.y);
                kd[(i >> 1) + 1] = __floats2half2_rn(a0.z, a0.w);
                kd[(i >> 1) + 2] = __floats2half2_rn(a1.x, a1.y);
                kd[(i >> 1) + 3] = __floats2half2_rn(a1.z, a1.w);
                float4 b0 = *(const float4*)(vr + i);
                float4 b1 = *(const float4*)(vr + i + 4);
                vd[(i >> 1) + 0] = __floats2half2_rn(b0.x, b0.y);
                vd[(i >> 1) + 1] = __floats2half2_rn(b0.z, b0.w);
                vd[(i >> 1) + 2] = __floats2half2_rn(b1.x, b1.y);
                vd[(i >> 1) + 3] = __floats2half2_rn(b1.z, b1.w);
            }
        }
        __syncthreads();

        /* S = Q K^T */
        float s[16][4];
        #pragma unroll
        for (int i = 0; i < 16; i++)
            #pragma unroll
            for (int r = 0; r < 4; r++) s[i][r] = 0.f;

        const uint32_t kb = smb + (uint32_t)(ASM_K * 2)
                          + (uint32_t)(((lane & 7) + ((lane >> 4) << 3)) * AROWP) * 2
                          + ((lane >> 3) & 1) * 16;
        #pragma unroll
        for (int kt = 0; kt < 4; kt++) {
            #pragma unroll
            for (int np = 0; np < 8; np++) {
                uint32_t bf[4];
                ldsm_x4(bf, kb + (uint32_t)(np * 16 * AROWP) * 2 + kt * 32);
                mma_f16(s[2 * np],     qa[kt], &bf[0]);
                mma_f16(s[2 * np + 1], qa[kt], &bf[2]);
            }
        }

        /* online softmax */
        float cx0 = -INFINITY, cx1 = -INFINITY;
        #pragma unroll
        for (int i = 0; i < 16; i++) {
            cx0 = fmaxf(cx0, fmaxf(s[i][0], s[i][1]));
            cx1 = fmaxf(cx1, fmaxf(s[i][2], s[i][3]));
        }
        cx0 = fmaxf(cx0, __shfl_xor_sync(0xFFFFFFFFu, cx0, 1));
        cx0 = fmaxf(cx0, __shfl_xor_sync(0xFFFFFFFFu, cx0, 2));
        cx1 = fmaxf(cx1, __shfl_xor_sync(0xFFFFFFFFu, cx1, 1));
        cx1 = fmaxf(cx1, __shfl_xor_sync(0xFFFFFFFFu, cx1, 2));
        const float mn0 = fmaxf(m0, cx0);
        const float mn1 = fmaxf(m1, cx1);
        const float cr0 = __expf(m0 - mn0);
        const float cr1 = __expf(m1 - mn1);
        l0 *= cr0; l1 *= cr1;
        #pragma unroll
        for (int i = 0; i < 8; i++) {
            o[i][0] *= cr0; o[i][1] *= cr0;
            o[i][2] *= cr1; o[i][3] *= cr1;
        }
        float sm0 = 0.f, sm1 = 0.f;
        #pragma unroll
        for (int i = 0; i < 16; i++) {
            s[i][0] = __expf(s[i][0] - mn0);
            s[i][1] = __expf(s[i][1] - mn0);
            s[i][2] = __expf(s[i][2] - mn1);
            s[i][3] = __expf(s[i][3] - mn1);
            sm0 += s[i][0] + s[i][1];
            sm1 += s[i][2] + s[i][3];
        }
        sm0 += __shfl_xor_sync(0xFFFFFFFFu, sm0, 1);
        sm0 += __shfl_xor_sync(0xFFFFFFFFu, sm0, 2);
        sm1 += __shfl_xor_sync(0xFFFFFFFFu, sm1, 1);
        sm1 += __shfl_xor_sync(0xFFFFFFFFu, sm1, 2);
        l0 += sm0; l1 += sm1;
        m0 = mn0; m1 = mn1;

        /* O += P V (ldmatrix.trans on V; db covers 16 dims each -> 4 blocks) */
        const uint32_t vb = smb + (uint32_t)(ASM_V * 2)
                          + (uint32_t)((lane & 15) * AROWP) * 2 + (lane >> 4) * 16;
        #pragma unroll
        for (int kt = 0; kt < 8; kt++) {
            __half2 t0 = __floats2half2_rn(s[2 * kt][0], s[2 * kt][1]);
            __half2 t1 = __floats2half2_rn(s[2 * kt][2], s[2 * kt][3]);
            __half2 t2 = __floats2half2_rn(s[2 * kt + 1][0], s[2 * kt + 1][1]);
            __half2 t3 = __floats2half2_rn(s[2 * kt + 1][2], s[2 * kt + 1][3]);
            uint32_t pa[4];
            pa[0] = *(uint32_t*)&t0;
            pa[1] = *(uint32_t*)&t1;
            pa[2] = *(uint32_t*)&t2;
            pa[3] = *(uint32_t*)&t3;
            #pragma unroll
            for (int db = 0; db < 4; db++) {
                uint32_t bt[4];
                ldsm_x4_t(bt, vb + (uint32_t)(kt * 16 * AROWP) * 2 + db * 32);
                mma_f16(o[db * 2],     pa, &bt[0]);
                mma_f16(o[db * 2 + 1], pa, &bt[2]);
            }
        }
    }

    /* epilogue */
    const float iv0 = 1.f / l0;
    const float iv1 = 1.f / l1;
    const int r0 = bi * WIN + wid * 16 + g;
    __half2* out0 = (__half2*)(out + ((size_t)(b * SEQ + r0)) * EMB + h * HD);
    __half2* out1 = (__half2*)(out + ((size_t)(b * SEQ + r0 + 8)) * EMB + h * HD);
    #pragma unroll
    for (int nt = 0; nt < 8; nt++) {
        const int c = (nt * 8 + tg * 2) >> 1;
        out0[c] = __floats2half2_rn(o[nt][0] * iv0, o[nt][1] * iv0);
        out1[c] = __floats2half2_rn(o[nt][2] * iv1, o[nt][3] * iv1);
    }
}

/* ---------------- launch ---------------- */
extern "C" void kernel_launch(void* const* d_in, const int* in_sizes, int n_in,
                              void* d_out, int out_size)
{
    const float* x     = (const float*)d_in[0];
    const float* ln1w  = (const float*)d_in[1];
    const float* ln1b  = (const float*)d_in[2];
    const float* qkvw  = (const float*)d_in[3];
    const float* qkvb  = (const float*)d_in[4];
    const float* projw = (const float*)d_in[5];
    const float* projb = (const float*)d_in[6];
    const float* ln2w  = (const float*)d_in[7];
    const float* ln2b  = (const float*)d_in[8];
    const float* fc1w  = (const float*)d_in[9];
    const float* fc1b  = (const float*)d_in[10];
    const float* fc2w  = (const float*)d_in[11];
    const float* fc2b  = (const float*)d_in[12];
    float* out = (float*)d_out;

    __half *xnh, *attnh, *hbufh, *wqh, *wph, *w1h, *w2h;
    float *qkv;
    cudaGetSymbolAddress((void**)&xnh,   g_xnh);
    cudaGetSymbolAddress((void**)&qkv,   g_qkv);
    cudaGetSymbolAddress((void**)&attnh, g_attnh);
    cudaGetSymbolAddress((void**)&hbufh, g_hbufh);
    cudaGetSymbolAddress((void**)&wqh,   g_wqh);
    cudaGetSymbolAddress((void**)&wph,   g_wph);
    cudaGetSymbolAddress((void**)&w1h,   g_w1h);
    cudaGetSymbolAddress((void**)&w2h,   g_w2h);

    cudaFuncSetAttribute(hgemm<EPI_NONE, 0>, cudaFuncAttributeMaxDynamicSharedMemorySize, HSMEM);
    cudaFuncSetAttribute(hgemm<EPI_ADD, 0>,  cudaFuncAttributeMaxDynamicSharedMemorySize, HSMEM);
    cudaFuncSetAttribute(hgemm<EPI_GELU, 1>, cudaFuncAttributeMaxDynamicSharedMemorySize, HSMEM);
    cudaFuncSetAttribute(lattn_mma, cudaFuncAttributeMaxDynamicSharedMemorySize, ASMEM);

    w2h_kernel<<<(3 * EMB * EMB / 4 + 255) / 256, 256>>>(qkvw, wqh, 3 * EMB * EMB / 4);
    w2h_kernel<<<(EMB * EMB / 4 + 255) / 256, 256>>>(projw, wph, EMB * EMB / 4);
    w2h_kernel<<<(DFF * EMB / 4 + 255) / 256, 256>>>(fc1w, w1h, DFF * EMB / 4);
    w2h_kernel<<<(EMB * DFF / 4 + 255) / 256, 256>>>(fc2w, w2h, EMB * DFF / 4);

    ln_kernel<<<M_TOK, 256>>>(x, ln1w, ln1b, xnh);
    hgemm<EPI_NONE, 0><<<dim3(3 * EMB / BN, M_TOK / BM), 256, HSMEM>>>(
        xnh, wqh, qkvb, nullptr, qkv, M_TOK, 3 * EMB, EMB);
    lattn_mma<<<dim3(NB, BATCH * HEADS), 256, ASMEM>>>(qkv, attnh);
    hgemm<EPI_ADD, 0><<<dim3(EMB / BN, M_TOK / BM), 256, HSMEM>>>(
        attnh, wph, projb, x, out, M_TOK, EMB, EMB);
    ln_kernel<<<M_TOK, 256>>>(out, ln2w, ln2b, xnh);
    hgemm<EPI_GELU, 1><<<dim3(DFF / BN, M_TOK / BM), 256, HSMEM>>>(
        xnh, w1h, fc1b, nullptr, hbufh, M_TOK, DFF, EMB);
    hgemm<EPI_ADD, 0><<<dim3(EMB / BN, M_TOK / BM), 256, HSMEM>>>(
        hbufh, w2h, fc2b, out, out, M_TOK, EMB, DFF);
}

// round 15
// speedup vs baseline: 1.8471x; 1.0515x over previous
#include <cuda_runtime.h>
#include <cuda_fp16.h>
#include <math.h>
#include <stdint.h>

#define BATCH   4
#define SEQ     4096
#define EMB     1024
#define HEADS   16
#define HD      64
#define DFF     4096
#define WIN     128
#define NB      (SEQ / WIN)
#define M_TOK   (BATCH * SEQ)

/* ---------------- scratch ---------------- */
__device__ __half g_xnh[(size_t)M_TOK * EMB];
__device__ __half g_qkvh[(size_t)M_TOK * 3 * EMB];   /* qkv as half (96MB) */
__device__ __half g_attnh[(size_t)M_TOK * EMB];
__device__ __half g_hbufh[(size_t)M_TOK * DFF];
__device__ __half g_wqh[(size_t)3 * EMB * EMB];
__device__ __half g_wph[(size_t)EMB * EMB];
__device__ __half g_w1h[(size_t)DFF * EMB];
__device__ __half g_w2h[(size_t)EMB * DFF];

/* ---------------- PTX helpers ---------------- */
__device__ __forceinline__ uint32_t smem_u32(const void* p)
{
    uint32_t a;
    asm("{ .reg .u64 t; cvta.to.shared.u64 t, %1; cvt.u32.u64 %0, t; }" : "=r"(a) : "l"(p));
    return a;
}
__device__ __forceinline__ void cp16(uint32_t s, const void* g)
{
    asm volatile("cp.async.cg.shared.global [%0], [%1], 16;" :: "r"(s), "l"(g));
}
__device__ __forceinline__ void cp_commit() { asm volatile("cp.async.commit_group;"); }
template<int N>
__device__ __forceinline__ void cp_wait() { asm volatile("cp.async.wait_group %0;" :: "n"(N)); }

__device__ __forceinline__ void ldsm_x4(uint32_t* r, uint32_t addr)
{
    asm volatile("ldmatrix.sync.aligned.m8n8.x4.shared.b16 {%0,%1,%2,%3}, [%4];"
                 : "=r"(r[0]), "=r"(r[1]), "=r"(r[2]), "=r"(r[3]) : "r"(addr));
}
__device__ __forceinline__ void ldsm_x4_t(uint32_t* r, uint32_t addr)
{
    asm volatile("ldmatrix.sync.aligned.m8n8.x4.trans.shared.b16 {%0,%1,%2,%3}, [%4];"
                 : "=r"(r[0]), "=r"(r[1]), "=r"(r[2]), "=r"(r[3]) : "r"(addr));
}
__device__ __forceinline__ void mma_f16(float* d, const uint32_t* a, const uint32_t* b)
{
    asm volatile(
        "mma.sync.aligned.m16n8k16.row.col.f32.f16.f16.f32 "
        "{%0,%1,%2,%3},{%4,%5,%6,%7},{%8,%9},{%0,%1,%2,%3};"
        : "+f"(d[0]), "+f"(d[1]), "+f"(d[2]), "+f"(d[3])
        : "r"(a[0]), "r"(a[1]), "r"(a[2]), "r"(a[3]), "r"(b[0]), "r"(b[1]));
}

/* ---------------- fp16 tensor-core GEMM (round-13 winner, unchanged) -------- */
#define BM 128
#define BN 128
#define BKD 32
#define ROWP 40
#define T_STG (128 * ROWP * 2)
#define HSMEM (3 * 2 * T_STG)

#define EPI_NONE 0
#define EPI_ADD  1
#define EPI_GELU 2

template<int EPI, int OUTH>
__global__ __launch_bounds__(256, 2)
void hgemm(const __half* __restrict__ A, const __half* __restrict__ B,
           const float* __restrict__ bias, const float* __restrict__ R,
           void* __restrict__ Cv, int M, int N, int K)
{
    extern __shared__ __align__(16) uint8_t dyn[];
    const uint32_t smem0 = smem_u32(dyn);
    const uint32_t aBase = smem0;
    const uint32_t bBase = smem0 + 3 * T_STG;

    const int tid = threadIdx.x;
    const int wid = tid >> 5;
    const int lane = tid & 31;
    const int g = lane >> 2;
    const int tg = lane & 3;
    const int bm = blockIdx.y * BM;
    const int bn = blockIdx.x * BN;
    const int warp_m = (wid & 1) * 64;
    const int warp_n = (wid >> 1) * 32;

    const int srow = tid >> 2;
    const int sseg = (tid & 3) * 8;

    const uint32_t a_lane = (uint32_t)((warp_m + (lane & 15)) * ROWP + (lane >> 4) * 8) * 2;
    const uint32_t b_lane = (uint32_t)((warp_n + (lane & 7) + (lane >> 4) * 8) * ROWP
                                       + ((lane >> 3) & 1) * 8) * 2;

    float acc[4][4][4];
    #pragma unroll
    for (int i = 0; i < 4; i++)
        #pragma unroll
        for (int j = 0; j < 4; j++)
            #pragma unroll
            for (int r = 0; r < 4; r++) acc[i][j][r] = 0.f;

    auto load_stage = [&](int s) {
        const int st = s % 3;
        const int k0 = s * BKD;
        #pragma unroll
        for (int i = 0; i < 2; i++) {
            const int row = srow + i * 64;
            cp16(aBase + st * T_STG + (uint32_t)(row * ROWP + sseg) * 2,
                 A + (size_t)(bm + row) * K + k0 + sseg);
            cp16(bBase + st * T_STG + (uint32_t)(row * ROWP + sseg) * 2,
                 B + (size_t)(bn + row) * K + k0 + sseg);
        }
        cp_commit();
    };

    const int S = K / BKD;
    load_stage(0);
    load_stage(1);

    for (int s = 0; s < S; s++) {
        if (s + 1 < S) cp_wait<1>(); else cp_wait<0>();
        __syncthreads();
        if (s + 2 < S) load_stage(s + 2);

        const int st = s % 3;
        const uint32_t aS = aBase + st * T_STG + a_lane;
        const uint32_t bS = bBase + st * T_STG + b_lane;

        #pragma unroll
        for (int ks = 0; ks < 2; ks++) {
            const uint32_t kc2 = ks * 32;
            uint32_t a[4][4], b[2][4];
            #pragma unroll
            for (int mt = 0; mt < 4; mt++)
                ldsm_x4(a[mt], aS + kc2 + mt * (16 * ROWP * 2));
            #pragma unroll
            for (int p = 0; p < 2; p++)
                ldsm_x4(b[p], bS + kc2 + p * (16 * ROWP * 2));
            #pragma unroll
            for (int mt = 0; mt < 4; mt++)
                #pragma unroll
                for (int nt = 0; nt < 4; nt++)
                    mma_f16(acc[mt][nt], a[mt], &b[nt >> 1][(nt & 1) * 2]);
        }
    }

    #pragma unroll
    for (int mt = 0; mt < 4; mt++) {
        #pragma unroll
        for (int h = 0; h < 2; h++) {
            const int row = bm + warp_m + mt * 16 + g + h * 8;
            #pragma unroll
            for (int nt = 0; nt < 4; nt++) {
                const int col = bn + warp_n + nt * 8 + tg * 2;
                float c0 = acc[mt][nt][h * 2 + 0];
                float c1 = acc[mt][nt][h * 2 + 1];
                const float2 bv = *(const float2*)(bias + col);
                c0 += bv.x; c1 += bv.y;
                if (EPI == EPI_ADD) {
                    const float2 rv = *(const float2*)(R + (size_t)row * N + col);
                    c0 += rv.x; c1 += rv.y;
                }
                if (EPI == EPI_GELU) {
                    c0 = 0.5f * c0 * (1.f + erff(c0 * 0.70710678118654752f));
                    c1 = 0.5f * c1 * (1.f + erff(c1 * 0.70710678118654752f));
                }
                if (OUTH) {
                    ((__half2*)Cv)[((size_t)row * N + col) >> 1] = __floats2half2_rn(c0, c1);
                } else {
                    float2 o; o.x = c0; o.y = c1;
                    *(float2*)((float*)Cv + (size_t)row * N + col) = o;
                }
            }
        }
    }
}

/* ---------------- weight fp32 -> half ---------------- */
__global__ __launch_bounds__(256)
void w2h_kernel(const float* __restrict__ src, __half* __restrict__ dst, int n4)
{
    const int i = blockIdx.x * 256 + threadIdx.x;
    if (i < n4) {
        float4 v = ((const float4*)src)[i];
        __half2* d = (__half2*)(dst + (size_t)i * 4);
        d[0] = __floats2half2_rn(v.x, v.y);
        d[1] = __floats2half2_rn(v.z, v.w);
    }
}

/* ---------------- block reduction ---------------- */
__device__ __forceinline__ float block_sum_1024(float v, float* sh)
{
    #pragma unroll
    for (int o = 16; o > 0; o >>= 1)
        v += __shfl_xor_sync(0xFFFFFFFFu, v, o);
    const int wid = threadIdx.x >> 5;
    const int lane = threadIdx.x & 31;
    if (lane == 0) sh[wid] = v;
    __syncthreads();
    if (wid == 0) {
        float t = (lane < 8) ? sh[lane] : 0.f;
        #pragma unroll
        for (int o = 4; o > 0; o >>= 1)
            t += __shfl_xor_sync(0xFFFFFFFFu, t, o);
        if (lane == 0) sh[8] = t;
    }
    __syncthreads();
    float r = sh[8];
    __syncthreads();
    return r;
}

/* ---------------- LayerNorm -> half ---------------- */
__global__ __launch_bounds__(256)
void ln_kernel(const float* __restrict__ x, const float* __restrict__ w,
               const float* __restrict__ b, __half* __restrict__ out)
{
    __shared__ float sh[9];
    const int row = blockIdx.x;
    const int t = threadIdx.x;
    const float* xr = x + (size_t)row * EMB;

    float4 v = *(const float4*)(xr + t * 4);
    float mu = block_sum_1024(v.x + v.y + v.z + v.w, sh) * (1.f / EMB);

    float d0 = v.x - mu, d1 = v.y - mu, d2 = v.z - mu, d3 = v.w - mu;
    float var = block_sum_1024(d0 * d0 + d1 * d1 + d2 * d2 + d3 * d3, sh) * (1.f / EMB);
    float rs = rsqrtf(var + 1e-5f);

    float4 wv = *(const float4*)(w + t * 4);
    float4 bv = *(const float4*)(b + t * 4);
    __half2* orow = (__half2*)(out + (size_t)row * EMB + t * 4);
    orow[0] = __floats2half2_rn(d0 * rs * wv.x + bv.x, d1 * rs * wv.y + bv.y);
    orow[1] = __floats2half2_rn(d2 * rs * wv.z + bv.z, d3 * rs * wv.w + bv.w);
}

/* ---------------- tensorized local attention (half in, cp.async, dbuf KV) --- */
#define AROWP 72
#define ABUF (128 * AROWP)            /* halves per 128-row buffer */
#define ASMEM (5 * ABUF * 2)          /* Q + 2xK + 2xV = 92160 B */

__global__ __launch_bounds__(256, 1)
void lattn_mma(const __half* __restrict__ qkv, __half* __restrict__ out)
{
    extern __shared__ __align__(16) __half sm[];
    const uint32_t smb = smem_u32(sm);

    const int bi = blockIdx.x;
    const int bh = blockIdx.y;
    const int b = bh >> 4, h = bh & 15;
    const int tid = threadIdx.x;
    const int wid = tid >> 5;
    const int lane = tid & 31;
    const int g = lane >> 2;
    const int tg = lane & 3;

    const __half* base = qkv + (size_t)b * SEQ * (3 * EMB);
    const int srow = tid >> 1;            /* 0..127 */
    const int scol = (tid & 1) * 32;      /* halves (64B) */

    /* stage Q once (cp.async, 4x16B per thread) */
    {
        const __half* qr = base + (size_t)(bi * WIN + srow) * (3 * EMB) + h * HD + scol;
        const uint32_t qd = smb + (uint32_t)(srow * AROWP + scol) * 2;
        #pragma unroll
        for (int i = 0; i < 4; i++)
            cp16(qd + i * 16, qr + i * 8);
        cp_commit();
    }

    auto stage_kv = [&](int sb) {
        const __half* kr = base + (size_t)(sb * WIN + srow) * (3 * EMB) + EMB + h * HD + scol;
        const __half* vr = kr + EMB;
        const int buf = sb & 1;
        const uint32_t kd = smb + (uint32_t)((1 + buf) * ABUF + srow * AROWP + scol) * 2;
        const uint32_t vd = smb + (uint32_t)((3 + buf) * ABUF + srow * AROWP + scol) * 2;
        #pragma unroll
        for (int i = 0; i < 4; i++) {
            cp16(kd + i * 16, kr + i * 8);
            cp16(vd + i * 16, vr + i * 8);
        }
        cp_commit();
    };

    const int sb_lo = (bi > 0) ? bi - 1 : 0;
    const int sb_hi = (bi < NB - 1) ? bi + 1 : NB - 1;
    stage_kv(sb_lo);

    uint32_t qa[4][4];
    float m0 = -INFINITY, m1 = -INFINITY, l0 = 0.f, l1 = 0.f;
    float o[8][4];
    #pragma unroll
    for (int i = 0; i < 8; i++)
        #pragma unroll
        for (int r = 0; r < 4; r++) o[i][r] = 0.f;

    for (int sb = sb_lo; sb <= sb_hi; sb++) {
        cp_wait<0>();
        __syncthreads();

        if (sb == sb_lo) {
            const uint32_t al = smb + (uint32_t)((wid * 16 + (lane & 15)) * AROWP) * 2
                              + (lane >> 4) * 16;
            #pragma unroll
            for (int kt = 0; kt < 4; kt++)
                ldsm_x4(qa[kt], al + kt * 32);
        }
        if (sb + 1 <= sb_hi) stage_kv(sb + 1);

        const int buf = sb & 1;

        /* S = Q K^T (scale 0.125 applied post-mma) */
        float s[16][4];
        #pragma unroll
        for (int i = 0; i < 16; i++)
            #pragma unroll
            for (int r = 0; r < 4; r++) s[i][r] = 0.f;

        const uint32_t kb = smb + (uint32_t)((1 + buf) * ABUF) * 2
                          + (uint32_t)(((lane & 7) + ((lane >> 4) << 3)) * AROWP) * 2
                          + ((lane >> 3) & 1) * 16;
        #pragma unroll
        for (int kt = 0; kt < 4; kt++) {
            #pragma unroll
            for (int np = 0; np < 8; np++) {
                uint32_t bf[4];
                ldsm_x4(bf, kb + (uint32_t)(np * 16 * AROWP) * 2 + kt * 32);
                mma_f16(s[2 * np],     qa[kt], &bf[0]);
                mma_f16(s[2 * np + 1], qa[kt], &bf[2]);
            }
        }
        #pragma unroll
        for (int i = 0; i < 16; i++) {
            s[i][0] *= 0.125f; s[i][1] *= 0.125f;
            s[i][2] *= 0.125f; s[i][3] *= 0.125f;
        }

        /* online softmax */
        float cx0 = -INFINITY, cx1 = -INFINITY;
        #pragma unroll
        for (int i = 0; i < 16; i++) {
            cx0 = fmaxf(cx0, fmaxf(s[i][0], s[i][1]));
            cx1 = fmaxf(cx1, fmaxf(s[i][2], s[i][3]));
        }
        cx0 = fmaxf(cx0, __shfl_xor_sync(0xFFFFFFFFu, cx0, 1));
        cx0 = fmaxf(cx0, __shfl_xor_sync(0xFFFFFFFFu, cx0, 2));
        cx1 = fmaxf(cx1, __shfl_xor_sync(0xFFFFFFFFu, cx1, 1));
        cx1 = fmaxf(cx1, __shfl_xor_sync(0xFFFFFFFFu, cx1, 2));
        const float mn0 = fmaxf(m0, cx0);
        const float mn1 = fmaxf(m1, cx1);
        const float cr0 = __expf(m0 - mn0);
        const float cr1 = __expf(m1 - mn1);
        l0 *= cr0; l1 *= cr1;
        #pragma unroll
        for (int i = 0; i < 8; i++) {
            o[i][0] *= cr0; o[i][1] *= cr0;
            o[i][2] *= cr1; o[i][3] *= cr1;
        }
        float sm0 = 0.f, sm1 = 0.f;
        #pragma unroll
        for (int i = 0; i < 16; i++) {
            s[i][0] = __expf(s[i][0] - mn0);
            s[i][1] = __expf(s[i][1] - mn0);
            s[i][2] = __expf(s[i][2] - mn1);
            s[i][3] = __expf(s[i][3] - mn1);
            sm0 += s[i][0] + s[i][1];
            sm1 += s[i][2] + s[i][3];
        }
        sm0 += __shfl_xor_sync(0xFFFFFFFFu, sm0, 1);
        sm0 += __shfl_xor_sync(0xFFFFFFFFu, sm0, 2);
        sm1 += __shfl_xor_sync(0xFFFFFFFFu, sm1, 1);
        sm1 += __shfl_xor_sync(0xFFFFFFFFu, sm1, 2);
        l0 += sm0; l1 += sm1;
        m0 = mn0; m1 = mn1;

        /* O += P V */
        const uint32_t vb = smb + (uint32_t)((3 + buf) * ABUF) * 2
                          + (uint32_t)((lane & 15) * AROWP) * 2 + (lane >> 4) * 16;
        #pragma unroll
        for (int kt = 0; kt < 8; kt++) {
            __half2 t0 = __floats2half2_rn(s[2 * kt][0], s[2 * kt][1]);
            __half2 t1 = __floats2half2_rn(s[2 * kt][2], s[2 * kt][3]);
            __half2 t2 = __floats2half2_rn(s[2 * kt + 1][0], s[2 * kt + 1][1]);
            __half2 t3 = __floats2half2_rn(s[2 * kt + 1][2], s[2 * kt + 1][3]);
            uint32_t pa[4];
            pa[0] = *(uint32_t*)&t0;
            pa[1] = *(uint32_t*)&t1;
            pa[2] = *(uint32_t*)&t2;
            pa[3] = *(uint32_t*)&t3;
            #pragma unroll
            for (int db = 0; db < 4; db++) {
                uint32_t bt[4];
                ldsm_x4_t(bt, vb + (uint32_t)(kt * 16 * AROWP) * 2 + db * 32);
                mma_f16(o[db * 2],     pa, &bt[0]);
                mma_f16(o[db * 2 + 1], pa, &bt[2]);
            }
        }
    }

    /* epilogue */
    const float iv0 = 1.f / l0;
    const float iv1 = 1.f / l1;
    const int r0 = bi * WIN + wid * 16 + g;
    __half2* out0 = (__half2*)(out + ((size_t)(b * SEQ + r0)) * EMB + h * HD);
    __half2* out1 = (__half2*)(out + ((size_t)(b * SEQ + r0 + 8)) * EMB + h * HD);
    #pragma unroll
    for (int nt = 0; nt < 8; nt++) {
        const int c = (nt * 8 + tg * 2) >> 1;
        out0[c] = __floats2half2_rn(o[nt][0] * iv0, o[nt][1] * iv0);
        out1[c] = __floats2half2_rn(o[nt][2] * iv1, o[nt][3] * iv1);
    }
}

/* ---------------- launch ---------------- */
extern "C" void kernel_launch(void* const* d_in, const int* in_sizes, int n_in,
                              void* d_out, int out_size)
{
    const float* x     = (const float*)d_in[0];
    const float* ln1w  = (const float*)d_in[1];
    const float* ln1b  = (const float*)d_in[2];
    const float* qkvw  = (const float*)d_in[3];
    const float* qkvb  = (const float*)d_in[4];
    const float* projw = (const float*)d_in[5];
    const float* projb = (const float*)d_in[6];
    const float* ln2w  = (const float*)d_in[7];
    const float* ln2b  = (const float*)d_in[8];
    const float* fc1w  = (const float*)d_in[9];
    const float* fc1b  = (const float*)d_in[10];
    const float* fc2w  = (const float*)d_in[11];
    const float* fc2b  = (const float*)d_in[12];
    float* out = (float*)d_out;

    __half *xnh, *qkvh, *attnh, *hbufh, *wqh, *wph, *w1h, *w2h;
    cudaGetSymbolAddress((void**)&xnh,   g_xnh);
    cudaGetSymbolAddress((void**)&qkvh,  g_qkvh);
    cudaGetSymbolAddress((void**)&attnh, g_attnh);
    cudaGetSymbolAddress((void**)&hbufh, g_hbufh);
    cudaGetSymbolAddress((void**)&wqh,   g_wqh);
    cudaGetSymbolAddress((void**)&wph,   g_wph);
    cudaGetSymbolAddress((void**)&w1h,   g_w1h);
    cudaGetSymbolAddress((void**)&w2h,   g_w2h);

    cudaFuncSetAttribute(hgemm<EPI_NONE, 1>, cudaFuncAttributeMaxDynamicSharedMemorySize, HSMEM);
    cudaFuncSetAttribute(hgemm<EPI_ADD, 0>,  cudaFuncAttributeMaxDynamicSharedMemorySize, HSMEM);
    cudaFuncSetAttribute(hgemm<EPI_GELU, 1>, cudaFuncAttributeMaxDynamicSharedMemorySize, HSMEM);
    cudaFuncSetAttribute(lattn_mma, cudaFuncAttributeMaxDynamicSharedMemorySize, ASMEM);

    w2h_kernel<<<(3 * EMB * EMB / 4 + 255) / 256, 256>>>(qkvw, wqh, 3 * EMB * EMB / 4);
    w2h_kernel<<<(EMB * EMB / 4 + 255) / 256, 256>>>(projw, wph, EMB * EMB / 4);
    w2h_kernel<<<(DFF * EMB / 4 + 255) / 256, 256>>>(fc1w, w1h, DFF * EMB / 4);
    w2h_kernel<<<(EMB * DFF / 4 + 255) / 256, 256>>>(fc2w, w2h, EMB * DFF / 4);

    ln_kernel<<<M_TOK, 256>>>(x, ln1w, ln1b, xnh);
    hgemm<EPI_NONE, 1><<<dim3(3 * EMB / BN, M_TOK / BM), 256, HSMEM>>>(
        xnh, wqh, qkvb, nullptr, qkvh, M_TOK, 3 * EMB, EMB);
    lattn_mma<<<dim3(NB, BATCH * HEADS), 256, ASMEM>>>(qkvh, attnh);
    hgemm<EPI_ADD, 0><<<dim3(EMB / BN, M_TOK / BM), 256, HSMEM>>>(
        attnh, wph, projb, x, out, M_TOK, EMB, EMB);
    ln_kernel<<<M_TOK, 256>>>(out, ln2w, ln2b, xnh);
    hgemm<EPI_GELU, 1><<<dim3(DFF / BN, M_TOK / BM), 256, HSMEM>>>(
        xnh, w1h, fc1b, nullptr, hbufh, M_TOK, DFF, EMB);
    hgemm<EPI_ADD, 0><<<dim3(EMB / BN, M_TOK / BM), 256, HSMEM>>>(
        hbufh, w2h, fc2b, out, out, M_TOK, EMB, DFF);
}

// round 16
// speedup vs baseline: 1.9706x; 1.0669x over previous
#include <cuda_runtime.h>
#include <cuda_fp16.h>
#include <math.h>
#include <stdint.h>

#define BATCH   4
#define SEQ     4096
#define EMB     1024
#define HEADS   16
#define HD      64
#define DFF     4096
#define WIN     128
#define NB      (SEQ / WIN)
#define M_TOK   (BATCH * SEQ)

/* ---------------- scratch ---------------- */
__device__ __half g_xnh[(size_t)M_TOK * EMB];
__device__ __half g_qkvh[(size_t)M_TOK * 3 * EMB];
__device__ __half g_attnh[(size_t)M_TOK * EMB];
__device__ __half g_hbufh[(size_t)M_TOK * DFF];
__device__ __half g_wqh[(size_t)3 * EMB * EMB];
__device__ __half g_wph[(size_t)EMB * EMB];
__device__ __half g_w1h[(size_t)DFF * EMB];
__device__ __half g_w2h[(size_t)EMB * DFF];

/* ---------------- PTX helpers ---------------- */
__device__ __forceinline__ uint32_t smem_u32(const void* p)
{
    uint32_t a;
    asm("{ .reg .u64 t; cvta.to.shared.u64 t, %1; cvt.u32.u64 %0, t; }" : "=r"(a) : "l"(p));
    return a;
}
__device__ __forceinline__ void cp16(uint32_t s, const void* g)
{
    asm volatile("cp.async.cg.shared.global [%0], [%1], 16;" :: "r"(s), "l"(g));
}
__device__ __forceinline__ void cp_commit() { asm volatile("cp.async.commit_group;"); }
template<int N>
__device__ __forceinline__ void cp_wait() { asm volatile("cp.async.wait_group %0;" :: "n"(N)); }

__device__ __forceinline__ void ldsm_x4(uint32_t* r, uint32_t addr)
{
    asm volatile("ldmatrix.sync.aligned.m8n8.x4.shared.b16 {%0,%1,%2,%3}, [%4];"
                 : "=r"(r[0]), "=r"(r[1]), "=r"(r[2]), "=r"(r[3]) : "r"(addr));
}
__device__ __forceinline__ void ldsm_x4_t(uint32_t* r, uint32_t addr)
{
    asm volatile("ldmatrix.sync.aligned.m8n8.x4.trans.shared.b16 {%0,%1,%2,%3}, [%4];"
                 : "=r"(r[0]), "=r"(r[1]), "=r"(r[2]), "=r"(r[3]) : "r"(addr));
}
__device__ __forceinline__ void mma_f16(float* d, const uint32_t* a, const uint32_t* b)
{
    asm volatile(
        "mma.sync.aligned.m16n8k16.row.col.f32.f16.f16.f32 "
        "{%0,%1,%2,%3},{%4,%5,%6,%7},{%8,%9},{%0,%1,%2,%3};"
        : "+f"(d[0]), "+f"(d[1]), "+f"(d[2]), "+f"(d[3])
        : "r"(a[0]), "r"(a[1]), "r"(a[2]), "r"(a[3]), "r"(b[0]), "r"(b[1]));
}

/* ---------------- fp16 tensor-core GEMM ----------------
 * C[M,N] = A[M,K] @ B[N,K]^T + bias (+epilogue); half in, fp32 accum.
 * CTA 128x128 (2 CTAs/SM), warp tile 64x32, BK=64 (4 ksteps),
 * 3-stage cp.async ring, single barrier/iter, ldmatrix.x4, pad-72 rows. */
#define BM 128
#define BN 128
#define BKD 64
#define ROWP 72                               /* padded halves per row (validated geometry) */
#define T_STG (128 * ROWP * 2)                /* 18432 B per operand stage */
#define HSMEM (3 * 2 * T_STG)                 /* 110592 B per CTA */

#define EPI_NONE 0
#define EPI_ADD  1
#define EPI_GELU 2

template<int EPI, int OUTH>
__global__ __launch_bounds__(256, 2)
void hgemm(const __half* __restrict__ A, const __half* __restrict__ B,
           const float* __restrict__ bias, const float* __restrict__ R,
           void* __restrict__ Cv, int M, int N, int K)
{
    extern __shared__ __align__(16) uint8_t dyn[];
    const uint32_t smem0 = smem_u32(dyn);
    const uint32_t aBase = smem0;
    const uint32_t bBase = smem0 + 3 * T_STG;

    const int tid = threadIdx.x;
    const int wid = tid >> 5;
    const int lane = tid & 31;
    const int g = lane >> 2;
    const int tg = lane & 3;
    const int bm = blockIdx.y * BM;
    const int bn = blockIdx.x * BN;
    const int warp_m = (wid & 1) * 64;
    const int warp_n = (wid >> 1) * 32;

    const uint32_t a_lane = (uint32_t)((warp_m + (lane & 15)) * ROWP + (lane >> 4) * 8) * 2;
    const uint32_t b_lane = (uint32_t)((warp_n + (lane & 7) + (lane >> 4) * 8) * ROWP
                                       + ((lane >> 3) & 1) * 8) * 2;

    float acc[4][4][4];
    #pragma unroll
    for (int i = 0; i < 4; i++)
        #pragma unroll
        for (int j = 0; j < 4; j++)
            #pragma unroll
            for (int r = 0; r < 4; r++) acc[i][j][r] = 0.f;

    /* staging: 128 rows x 128B per operand = 1024 x 16B chunks; 4/thread/operand
       chunk c: row = c>>3 (0..127), seg = c&7 (16B units) */
    auto load_stage = [&](int s) {
        const int st = s % 3;
        const int k0 = s * BKD;
        #pragma unroll
        for (int i = 0; i < 4; i++) {
            const int c = tid + i * 256;
            const int row = c >> 3;
            const int sg8 = (c & 7) * 8;      /* halves offset */
            cp16(aBase + st * T_STG + (uint32_t)(row * ROWP + sg8) * 2,
                 A + (size_t)(bm + row) * K + k0 + sg8);
            cp16(bBase + st * T_STG + (uint32_t)(row * ROWP + sg8) * 2,
                 B + (size_t)(bn + row) * K + k0 + sg8);
        }
        cp_commit();
    };

    const int S = K / BKD;
    load_stage(0);
    load_stage(1);

    for (int s = 0; s < S; s++) {
        if (s + 1 < S) cp_wait<1>(); else cp_wait<0>();
        __syncthreads();
        if (s + 2 < S) load_stage(s + 2);

        const int st = s % 3;
        const uint32_t aS = aBase + st * T_STG + a_lane;
        const uint32_t bS = bBase + st * T_STG + b_lane;

        #pragma unroll
        for (int ks = 0; ks < 4; ks++) {
            const uint32_t kc2 = ks * 32;     /* 16 halves = 32 bytes */
            uint32_t a[4][4], b[2][4];
            #pragma unroll
            for (int mt = 0; mt < 4; mt++)
                ldsm_x4(a[mt], aS + kc2 + mt * (16 * ROWP * 2));
            #pragma unroll
            for (int p = 0; p < 2; p++)
                ldsm_x4(b[p], bS + kc2 + p * (16 * ROWP * 2));
            #pragma unroll
            for (int mt = 0; mt < 4; mt++)
                #pragma unroll
                for (int nt = 0; nt < 4; nt++)
                    mma_f16(acc[mt][nt], a[mt], &b[nt >> 1][(nt & 1) * 2]);
        }
    }

    #pragma unroll
    for (int mt = 0; mt < 4; mt++) {
        #pragma unroll
        for (int h = 0; h < 2; h++) {
            const int row = bm + warp_m + mt * 16 + g + h * 8;
            #pragma unroll
            for (int nt = 0; nt < 4; nt++) {
                const int col = bn + warp_n + nt * 8 + tg * 2;
                float c0 = acc[mt][nt][h * 2 + 0];
                float c1 = acc[mt][nt][h * 2 + 1];
                const float2 bv = *(const float2*)(bias + col);
                c0 += bv.x; c1 += bv.y;
                if (EPI == EPI_ADD) {
                    const float2 rv = *(const float2*)(R + (size_t)row * N + col);
                    c0 += rv.x; c1 += rv.y;
                }
                if (EPI == EPI_GELU) {
                    c0 = 0.5f * c0 * (1.f + erff(c0 * 0.70710678118654752f));
                    c1 = 0.5f * c1 * (1.f + erff(c1 * 0.70710678118654752f));
                }
                if (OUTH) {
                    ((__half2*)Cv)[((size_t)row * N + col) >> 1] = __floats2half2_rn(c0, c1);
                } else {
                    float2 o; o.x = c0; o.y = c1;
                    *(float2*)((float*)Cv + (size_t)row * N + col) = o;
                }
            }
        }
    }
}

/* ---------------- weight fp32 -> half ---------------- */
__global__ __launch_bounds__(256)
void w2h_kernel(const float* __restrict__ src, __half* __restrict__ dst, int n4)
{
    const int i = blockIdx.x * 256 + threadIdx.x;
    if (i < n4) {
        float4 v = ((const float4*)src)[i];
        __half2* d = (__half2*)(dst + (size_t)i * 4);
        d[0] = __floats2half2_rn(v.x, v.y);
        d[1] = __floats2half2_rn(v.z, v.w);
    }
}

/* ---------------- block reduction ---------------- */
__device__ __forceinline__ float block_sum_1024(float v, float* sh)
{
    #pragma unroll
    for (int o = 16; o > 0; o >>= 1)
        v += __shfl_xor_sync(0xFFFFFFFFu, v, o);
    const int wid = threadIdx.x >> 5;
    const int lane = threadIdx.x & 31;
    if (lane == 0) sh[wid] = v;
    __syncthreads();
    if (wid == 0) {
        float t = (lane < 8) ? sh[lane] : 0.f;
        #pragma unroll
        for (int o = 4; o > 0; o >>= 1)
            t += __shfl_xor_sync(0xFFFFFFFFu, t, o);
        if (lane == 0) sh[8] = t;
    }
    __syncthreads();
    float r = sh[8];
    __syncthreads();
    return r;
}

/* ---------------- LayerNorm -> half ---------------- */
__global__ __launch_bounds__(256)
void ln_kernel(const float* __restrict__ x, const float* __restrict__ w,
               const float* __restrict__ b, __half* __restrict__ out)
{
    __shared__ float sh[9];
    const int row = blockIdx.x;
    const int t = threadIdx.x;
    const float* xr = x + (size_t)row * EMB;

    float4 v = *(const float4*)(xr + t * 4);
    float mu = block_sum_1024(v.x + v.y + v.z + v.w, sh) * (1.f / EMB);

    float d0 = v.x - mu, d1 = v.y - mu, d2 = v.z - mu, d3 = v.w - mu;
    float var = block_sum_1024(d0 * d0 + d1 * d1 + d2 * d2 + d3 * d3, sh) * (1.f / EMB);
    float rs = rsqrtf(var + 1e-5f);

    float4 wv = *(const float4*)(w + t * 4);
    float4 bv = *(const float4*)(b + t * 4);
    __half2* orow = (__half2*)(out + (size_t)row * EMB + t * 4);
    orow[0] = __floats2half2_rn(d0 * rs * wv.x + bv.x, d1 * rs * wv.y + bv.y);
    orow[1] = __floats2half2_rn(d2 * rs * wv.z + bv.z, d3 * rs * wv.w + bv.w);
}

/* ---------------- tensorized local attention (half in, cp.async, dbuf KV) --- */
#define AROWP 72
#define ABUF (128 * AROWP)
#define ASMEM (5 * ABUF * 2)          /* Q + 2xK + 2xV = 92160 B */

__global__ __launch_bounds__(256, 1)
void lattn_mma(const __half* __restrict__ qkv, __half* __restrict__ out)
{
    extern __shared__ __align__(16) __half sm[];
    const uint32_t smb = smem_u32(sm);

    const int bi = blockIdx.x;
    const int bh = blockIdx.y;
    const int b = bh >> 4, h = bh & 15;
    const int tid = threadIdx.x;
    const int wid = tid >> 5;
    const int lane = tid & 31;
    const int g = lane >> 2;
    const int tg = lane & 3;

    const __half* base = qkv + (size_t)b * SEQ * (3 * EMB);
    const int srow = tid >> 1;
    const int scol = (tid & 1) * 32;

    {
        const __half* qr = base + (size_t)(bi * WIN + srow) * (3 * EMB) + h * HD + scol;
        const uint32_t qd = smb + (uint32_t)(srow * AROWP + scol) * 2;
        #pragma unroll
        for (int i = 0; i < 4; i++)
            cp16(qd + i * 16, qr + i * 8);
        cp_commit();
    }

    auto stage_kv = [&](int sb) {
        const __half* kr = base + (size_t)(sb * WIN + srow) * (3 * EMB) + EMB + h * HD + scol;
        const __half* vr = kr + EMB;
        const int buf = sb & 1;
        const uint32_t kd = smb + (uint32_t)((1 + buf) * ABUF + srow * AROWP + scol) * 2;
        const uint32_t vd = smb + (uint32_t)((3 + buf) * ABUF + srow * AROWP + scol) * 2;
        #pragma unroll
        for (int i = 0; i < 4; i++) {
            cp16(kd + i * 16, kr + i * 8);
            cp16(vd + i * 16, vr + i * 8);
        }
        cp_commit();
    };

    const int sb_lo = (bi > 0) ? bi - 1 : 0;
    const int sb_hi = (bi < NB - 1) ? bi + 1 : NB - 1;
    stage_kv(sb_lo);

    uint32_t qa[4][4];
    float m0 = -INFINITY, m1 = -INFINITY, l0 = 0.f, l1 = 0.f;
    float o[8][4];
    #pragma unroll
    for (int i = 0; i < 8; i++)
        #pragma unroll
        for (int r = 0; r < 4; r++) o[i][r] = 0.f;

    for (int sb = sb_lo; sb <= sb_hi; sb++) {
        cp_wait<0>();
        __syncthreads();

        if (sb == sb_lo) {
            const uint32_t al = smb + (uint32_t)((wid * 16 + (lane & 15)) * AROWP) * 2
                              + (lane >> 4) * 16;
            #pragma unroll
            for (int kt = 0; kt < 4; kt++)
                ldsm_x4(qa[kt], al + kt * 32);
        }
        if (sb + 1 <= sb_hi) stage_kv(sb + 1);

        const int buf = sb & 1;

        float s[16][4];
        #pragma unroll
        for (int i = 0; i < 16; i++)
            #pragma unroll
            for (int r = 0; r < 4; r++) s[i][r] = 0.f;

        const uint32_t kb = smb + (uint32_t)((1 + buf) * ABUF) * 2
                          + (uint32_t)(((lane & 7) + ((lane >> 4) << 3)) * AROWP) * 2
                          + ((lane >> 3) & 1) * 16;
        #pragma unroll
        for (int kt = 0; kt < 4; kt++) {
            #pragma unroll
            for (int np = 0; np < 8; np++) {
                uint32_t bf[4];
                ldsm_x4(bf, kb + (uint32_t)(np * 16 * AROWP) * 2 + kt * 32);
                mma_f16(s[2 * np],     qa[kt], &bf[0]);
                mma_f16(s[2 * np + 1], qa[kt], &bf[2]);
            }
        }
        #pragma unroll
        for (int i = 0; i < 16; i++) {
            s[i][0] *= 0.125f; s[i][1] *= 0.125f;
            s[i][2] *= 0.125f; s[i][3] *= 0.125f;
        }

        float cx0 = -INFINITY, cx1 = -INFINITY;
        #pragma unroll
        for (int i = 0; i < 16; i++) {
            cx0 = fmaxf(cx0, fmaxf(s[i][0], s[i][1]));
            cx1 = fmaxf(cx1, fmaxf(s[i][2], s[i][3]));
        }
        cx0 = fmaxf(cx0, __shfl_xor_sync(0xFFFFFFFFu, cx0, 1));
        cx0 = fmaxf(cx0, __shfl_xor_sync(0xFFFFFFFFu, cx0, 2));
        cx1 = fmaxf(cx1, __shfl_xor_sync(0xFFFFFFFFu, cx1, 1));
        cx1 = fmaxf(cx1, __shfl_xor_sync(0xFFFFFFFFu, cx1, 2));
        const float mn0 = fmaxf(m0, cx0);
        const float mn1 = fmaxf(m1, cx1);
        const float cr0 = __expf(m0 - mn0);
        const float cr1 = __expf(m1 - mn1);
        l0 *= cr0; l1 *= cr1;
        #pragma unroll
        for (int i = 0; i < 8; i++) {
            o[i][0] *= cr0; o[i][1] *= cr0;
            o[i][2] *= cr1; o[i][3] *= cr1;
        }
        float sm0 = 0.f, sm1 = 0.f;
        #pragma unroll
        for (int i = 0; i < 16; i++) {
            s[i][0] = __expf(s[i][0] - mn0);
            s[i][1] = __expf(s[i][1] - mn0);
            s[i][2] = __expf(s[i][2] - mn1);
            s[i][3] = __expf(s[i][3] - mn1);
            sm0 += s[i][0] + s[i][1];
            sm1 += s[i][2] + s[i][3];
        }
        sm0 += __shfl_xor_sync(0xFFFFFFFFu, sm0, 1);
        sm0 += __shfl_xor_sync(0xFFFFFFFFu, sm0, 2);
        sm1 += __shfl_xor_sync(0xFFFFFFFFu, sm1, 1);
        sm1 += __shfl_xor_sync(0xFFFFFFFFu, sm1, 2);
        l0 += sm0; l1 += sm1;
        m0 = mn0; m1 = mn1;

        const uint32_t vb = smb + (uint32_t)((3 + buf) * ABUF) * 2
                          + (uint32_t)((lane & 15) * AROWP) * 2 + (lane >> 4) * 16;
        #pragma unroll
        for (int kt = 0; kt < 8; kt++) {
            __half2 t0 = __floats2half2_rn(s[2 * kt][0], s[2 * kt][1]);
            __half2 t1 = __floats2half2_rn(s[2 * kt][2], s[2 * kt][3]);
            __half2 t2 = __floats2half2_rn(s[2 * kt + 1][0], s[2 * kt + 1][1]);
            __half2 t3 = __floats2half2_rn(s[2 * kt + 1][2], s[2 * kt + 1][3]);
            uint32_t pa[4];
            pa[0] = *(uint32_t*)&t0;
            pa[1] = *(uint32_t*)&t1;
            pa[2] = *(uint32_t*)&t2;
            pa[3] = *(uint32_t*)&t3;
            #pragma unroll
            for (int db = 0; db < 4; db++) {
                uint32_t bt[4];
                ldsm_x4_t(bt, vb + (uint32_t)(kt * 16 * AROWP) * 2 + db * 32);
                mma_f16(o[db * 2],     pa, &bt[0]);
                mma_f16(o[db * 2 + 1], pa, &bt[2]);
            }
        }
    }

    const float iv0 = 1.f / l0;
    const float iv1 = 1.f / l1;
    const int r0 = bi * WIN + wid * 16 + g;
    __half2* out0 = (__half2*)(out + ((size_t)(b * SEQ + r0)) * EMB + h * HD);
    __half2* out1 = (__half2*)(out + ((size_t)(b * SEQ + r0 + 8)) * EMB + h * HD);
    #pragma unroll
    for (int nt = 0; nt < 8; nt++) {
        const int c = (nt * 8 + tg * 2) >> 1;
        out0[c] = __floats2half2_rn(o[nt][0] * iv0, o[nt][1] * iv0);
        out1[c] = __floats2half2_rn(o[nt][2] * iv1, o[nt][3] * iv1);
    }
}

/* ---------------- launch ---------------- */
extern "C" void kernel_launch(void* const* d_in, const int* in_sizes, int n_in,
                              void* d_out, int out_size)
{
    const float* x     = (const float*)d_in[0];
    const float* ln1w  = (const float*)d_in[1];
    const float* ln1b  = (const float*)d_in[2];
    const float* qkvw  = (const float*)d_in[3];
    const float* qkvb  = (const float*)d_in[4];
    const float* projw = (const float*)d_in[5];
    const float* projb = (const float*)d_in[6];
    const float* ln2w  = (const float*)d_in[7];
    const float* ln2b  = (const float*)d_in[8];
    const float* fc1w  = (const float*)d_in[9];
    const float* fc1b  = (const float*)d_in[10];
    const float* fc2w  = (const float*)d_in[11];
    const float* fc2b  = (const float*)d_in[12];
    float* out = (float*)d_out;

    __half *xnh, *qkvh, *attnh, *hbufh, *wqh, *wph, *w1h, *w2h;
    cudaGetSymbolAddress((void**)&xnh,   g_xnh);
    cudaGetSymbolAddress((void**)&qkvh,  g_qkvh);
    cudaGetSymbolAddress((void**)&attnh, g_attnh);
    cudaGetSymbolAddress((void**)&hbufh, g_hbufh);
    cudaGetSymbolAddress((void**)&wqh,   g_wqh);
    cudaGetSymbolAddress((void**)&wph,   g_wph);
    cudaGetSymbolAddress((void**)&w1h,   g_w1h);
    cudaGetSymbolAddress((void**)&w2h,   g_w2h);

    cudaFuncSetAttribute(hgemm<EPI_NONE, 1>, cudaFuncAttributeMaxDynamicSharedMemorySize, HSMEM);
    cudaFuncSetAttribute(hgemm<EPI_ADD, 0>,  cudaFuncAttributeMaxDynamicSharedMemorySize, HSMEM);
    cudaFuncSetAttribute(hgemm<EPI_GELU, 1>, cudaFuncAttributeMaxDynamicSharedMemorySize, HSMEM);
    cudaFuncSetAttribute(lattn_mma, cudaFuncAttributeMaxDynamicSharedMemorySize, ASMEM);

    w2h_kernel<<<(3 * EMB * EMB / 4 + 255) / 256, 256>>>(qkvw, wqh, 3 * EMB * EMB / 4);
    w2h_kernel<<<(EMB * EMB / 4 + 255) / 256, 256>>>(projw, wph, EMB * EMB / 4);
    w2h_kernel<<<(DFF * EMB / 4 + 255) / 256, 256>>>(fc1w, w1h, DFF * EMB / 4);
    w2h_kernel<<<(EMB * DFF / 4 + 255) / 256, 256>>>(fc2w, w2h, EMB * DFF / 4);

    ln_kernel<<<M_TOK, 256>>>(x, ln1w, ln1b, xnh);
    hgemm<EPI_NONE, 1><<<dim3(3 * EMB / BN, M_TOK / BM), 256, HSMEM>>>(
        xnh, wqh, qkvb, nullptr, qkvh, M_TOK, 3 * EMB, EMB);
    lattn_mma<<<dim3(NB, BATCH * HEADS), 256, ASMEM>>>(qkvh, attnh);
    hgemm<EPI_ADD, 0><<<dim3(EMB / BN, M_TOK / BM), 256, HSMEM>>>(
        attnh, wph, projb, x, out, M_TOK, EMB, EMB);
    ln_kernel<<<M_TOK, 256>>>(out, ln2w, ln2b, xnh);
    hgemm<EPI_GELU, 1><<<dim3(DFF / BN, M_TOK / BM), 256, HSMEM>>>(
        xnh, w1h, fc1b, nullptr, hbufh, M_TOK, DFF, EMB);
    hgemm<EPI_ADD, 0><<<dim3(EMB / BN, M_TOK / BM), 256, HSMEM>>>(
        hbufh, w2h, fc2b, out, out, M_TOK, EMB, DFF);
}

// round 17
// speedup vs baseline: 1.9820x; 1.0058x over previous
#include <cuda_runtime.h>
#include <cuda_fp16.h>
#include <math.h>
#include <stdint.h>

#define BATCH   4
#define SEQ     4096
#define EMB     1024
#define HEADS   16
#define HD      64
#define DFF     4096
#define WIN     128
#define NB      (SEQ / WIN)
#define M_TOK   (BATCH * SEQ)

/* ---------------- scratch ---------------- */
__device__ __half g_xnh[(size_t)M_TOK * EMB];
__device__ __half g_qkvh[(size_t)M_TOK * 3 * EMB];
__device__ __half g_attnh[(size_t)M_TOK * EMB];
__device__ __half g_x1h[(size_t)M_TOK * EMB];        /* post-proj residual (half) */
__device__ __half g_hbufh[(size_t)M_TOK * DFF];
__device__ __half g_wqh[(size_t)3 * EMB * EMB];
__device__ __half g_wph[(size_t)EMB * EMB];
__device__ __half g_w1h[(size_t)DFF * EMB];
__device__ __half g_w2h[(size_t)EMB * DFF];

/* ---------------- PTX helpers ---------------- */
__device__ __forceinline__ uint32_t smem_u32(const void* p)
{
    uint32_t a;
    asm("{ .reg .u64 t; cvta.to.shared.u64 t, %1; cvt.u32.u64 %0, t; }" : "=r"(a) : "l"(p));
    return a;
}
__device__ __forceinline__ void cp16(uint32_t s, const void* g)
{
    asm volatile("cp.async.cg.shared.global [%0], [%1], 16;" :: "r"(s), "l"(g));
}
__device__ __forceinline__ void cp_commit() { asm volatile("cp.async.commit_group;"); }
template<int N>
__device__ __forceinline__ void cp_wait() { asm volatile("cp.async.wait_group %0;" :: "n"(N)); }

__device__ __forceinline__ void ldsm_x4(uint32_t* r, uint32_t addr)
{
    asm volatile("ldmatrix.sync.aligned.m8n8.x4.shared.b16 {%0,%1,%2,%3}, [%4];"
                 : "=r"(r[0]), "=r"(r[1]), "=r"(r[2]), "=r"(r[3]) : "r"(addr));
}
__device__ __forceinline__ void ldsm_x4_t(uint32_t* r, uint32_t addr)
{
    asm volatile("ldmatrix.sync.aligned.m8n8.x4.trans.shared.b16 {%0,%1,%2,%3}, [%4];"
                 : "=r"(r[0]), "=r"(r[1]), "=r"(r[2]), "=r"(r[3]) : "r"(addr));
}
__device__ __forceinline__ void mma_f16(float* d, const uint32_t* a, const uint32_t* b)
{
    asm volatile(
        "mma.sync.aligned.m16n8k16.row.col.f32.f16.f16.f32 "
        "{%0,%1,%2,%3},{%4,%5,%6,%7},{%8,%9},{%0,%1,%2,%3};"
        : "+f"(d[0]), "+f"(d[1]), "+f"(d[2]), "+f"(d[3])
        : "r"(a[0]), "r"(a[1]), "r"(a[2]), "r"(a[3]), "r"(b[0]), "r"(b[1]));
}

/* ---------------- fp16 tensor-core GEMM ----------------
 * C[M,N] = A[M,K] @ B[N,K]^T + bias (+epilogue); half in, fp32 accum.
 * CTA 128x128 (2 CTAs/SM), warp tile 64x32, BK=64, 3-stage ring,
 * single barrier/iter, ldmatrix.x4, pad-72 rows. RH: residual is half. */
#define BM 128
#define BN 128
#define BKD 64
#define ROWP 72
#define T_STG (128 * ROWP * 2)
#define HSMEM (3 * 2 * T_STG)

#define EPI_NONE 0
#define EPI_ADD  1
#define EPI_GELU 2

template<int EPI, int OUTH, int RH>
__global__ __launch_bounds__(256, 2)
void hgemm(const __half* __restrict__ A, const __half* __restrict__ B,
           const float* __restrict__ bias, const void* __restrict__ R,
           void* __restrict__ Cv, int M, int N, int K)
{
    extern __shared__ __align__(16) uint8_t dyn[];
    const uint32_t smem0 = smem_u32(dyn);
    const uint32_t aBase = smem0;
    const uint32_t bBase = smem0 + 3 * T_STG;

    const int tid = threadIdx.x;
    const int wid = tid >> 5;
    const int lane = tid & 31;
    const int g = lane >> 2;
    const int tg = lane & 3;
    const int bm = blockIdx.y * BM;
    const int bn = blockIdx.x * BN;
    const int warp_m = (wid & 1) * 64;
    const int warp_n = (wid >> 1) * 32;

    const uint32_t a_lane = (uint32_t)((warp_m + (lane & 15)) * ROWP + (lane >> 4) * 8) * 2;
    const uint32_t b_lane = (uint32_t)((warp_n + (lane & 7) + (lane >> 4) * 8) * ROWP
                                       + ((lane >> 3) & 1) * 8) * 2;

    float acc[4][4][4];
    #pragma unroll
    for (int i = 0; i < 4; i++)
        #pragma unroll
        for (int j = 0; j < 4; j++)
            #pragma unroll
            for (int r = 0; r < 4; r++) acc[i][j][r] = 0.f;

    auto load_stage = [&](int s) {
        const int st = s % 3;
        const int k0 = s * BKD;
        #pragma unroll
        for (int i = 0; i < 4; i++) {
            const int c = tid + i * 256;
            const int row = c >> 3;
            const int sg8 = (c & 7) * 8;
            cp16(aBase + st * T_STG + (uint32_t)(row * ROWP + sg8) * 2,
                 A + (size_t)(bm + row) * K + k0 + sg8);
            cp16(bBase + st * T_STG + (uint32_t)(row * ROWP + sg8) * 2,
                 B + (size_t)(bn + row) * K + k0 + sg8);
        }
        cp_commit();
    };

    const int S = K / BKD;
    load_stage(0);
    load_stage(1);

    for (int s = 0; s < S; s++) {
        if (s + 1 < S) cp_wait<1>(); else cp_wait<0>();
        __syncthreads();
        if (s + 2 < S) load_stage(s + 2);

        const int st = s % 3;
        const uint32_t aS = aBase + st * T_STG + a_lane;
        const uint32_t bS = bBase + st * T_STG + b_lane;

        #pragma unroll
        for (int ks = 0; ks < 4; ks++) {
            const uint32_t kc2 = ks * 32;
            uint32_t a[4][4], b[2][4];
            #pragma unroll
            for (int mt = 0; mt < 4; mt++)
                ldsm_x4(a[mt], aS + kc2 + mt * (16 * ROWP * 2));
            #pragma unroll
            for (int p = 0; p < 2; p++)
                ldsm_x4(b[p], bS + kc2 + p * (16 * ROWP * 2));
            #pragma unroll
            for (int mt = 0; mt < 4; mt++)
                #pragma unroll
                for (int nt = 0; nt < 4; nt++)
                    mma_f16(acc[mt][nt], a[mt], &b[nt >> 1][(nt & 1) * 2]);
        }
    }

    #pragma unroll
    for (int mt = 0; mt < 4; mt++) {
        #pragma unroll
        for (int h = 0; h < 2; h++) {
            const int row = bm + warp_m + mt * 16 + g + h * 8;
            #pragma unroll
            for (int nt = 0; nt < 4; nt++) {
                const int col = bn + warp_n + nt * 8 + tg * 2;
                float c0 = acc[mt][nt][h * 2 + 0];
                float c1 = acc[mt][nt][h * 2 + 1];
                const float2 bv = *(const float2*)(bias + col);
                c0 += bv.x; c1 += bv.y;
                if (EPI == EPI_ADD) {
                    if (RH) {
                        const __half2 rv = ((const __half2*)R)[((size_t)row * N + col) >> 1];
                        c0 += __half2float(__low2half(rv));
                        c1 += __half2float(__high2half(rv));
                    } else {
                        const float2 rv = *(const float2*)((const float*)R + (size_t)row * N + col);
                        c0 += rv.x; c1 += rv.y;
                    }
                }
                if (EPI == EPI_GELU) {
                    c0 = 0.5f * c0 * (1.f + erff(c0 * 0.70710678118654752f));
                    c1 = 0.5f * c1 * (1.f + erff(c1 * 0.70710678118654752f));
                }
                if (OUTH) {
                    ((__half2*)Cv)[((size_t)row * N + col) >> 1] = __floats2half2_rn(c0, c1);
                } else {
                    float2 o; o.x = c0; o.y = c1;
                    *(float2*)((float*)Cv + (size_t)row * N + col) = o;
                }
            }
        }
    }
}

/* ---------------- merged weight fp32 -> half (4 tensors, 1 launch) ---------- */
#define W_N0 (3 * EMB * EMB / 4)
#define W_N1 (EMB * EMB / 4)
#define W_N2 (DFF * EMB / 4)
#define W_N3 (EMB * DFF / 4)
#define W_TOT (W_N0 + W_N1 + W_N2 + W_N3)

__global__ __launch_bounds__(256)
void w2h_all(const float* __restrict__ s0, __half* __restrict__ d0,
             const float* __restrict__ s1, __half* __restrict__ d1,
             const float* __restrict__ s2, __half* __restrict__ d2,
             const float* __restrict__ s3, __half* __restrict__ d3)
{
    int i = blockIdx.x * 256 + threadIdx.x;
    if (i >= W_TOT) return;
    const float* src;
    __half* dst;
    if (i < W_N0) { src = s0; dst = d0; }
    else if ((i -= W_N0) < W_N1) { src = s1; dst = d1; }
    else if ((i -= W_N1) < W_N2) { src = s2; dst = d2; }
    else { i -= W_N2; src = s3; dst = d3; }
    float4 v = ((const float4*)src)[i];
    __half2* d = (__half2*)(dst + (size_t)i * 4);
    d[0] = __floats2half2_rn(v.x, v.y);
    d[1] = __floats2half2_rn(v.z, v.w);
}

/* ---------------- block reduction ---------------- */
__device__ __forceinline__ float block_sum_1024(float v, float* sh)
{
    #pragma unroll
    for (int o = 16; o > 0; o >>= 1)
        v += __shfl_xor_sync(0xFFFFFFFFu, v, o);
    const int wid = threadIdx.x >> 5;
    const int lane = threadIdx.x & 31;
    if (lane == 0) sh[wid] = v;
    __syncthreads();
    if (wid == 0) {
        float t = (lane < 8) ? sh[lane] : 0.f;
        #pragma unroll
        for (int o = 4; o > 0; o >>= 1)
            t += __shfl_xor_sync(0xFFFFFFFFu, t, o);
        if (lane == 0) sh[8] = t;
    }
    __syncthreads();
    float r = sh[8];
    __syncthreads();
    return r;
}

/* ---------------- LayerNorm (fp32 in) -> half ---------------- */
__global__ __launch_bounds__(256)
void ln_kernel(const float* __restrict__ x, const float* __restrict__ w,
               const float* __restrict__ b, __half* __restrict__ out)
{
    __shared__ float sh[9];
    const int row = blockIdx.x;
    const int t = threadIdx.x;
    const float* xr = x + (size_t)row * EMB;

    float4 v = *(const float4*)(xr + t * 4);
    float mu = block_sum_1024(v.x + v.y + v.z + v.w, sh) * (1.f / EMB);

    float d0 = v.x - mu, d1 = v.y - mu, d2 = v.z - mu, d3 = v.w - mu;
    float var = block_sum_1024(d0 * d0 + d1 * d1 + d2 * d2 + d3 * d3, sh) * (1.f / EMB);
    float rs = rsqrtf(var + 1e-5f);

    float4 wv = *(const float4*)(w + t * 4);
    float4 bv = *(const float4*)(b + t * 4);
    __half2* orow = (__half2*)(out + (size_t)row * EMB + t * 4);
    orow[0] = __floats2half2_rn(d0 * rs * wv.x + bv.x, d1 * rs * wv.y + bv.y);
    orow[1] = __floats2half2_rn(d2 * rs * wv.z + bv.z, d3 * rs * wv.w + bv.w);
}

/* ---------------- LayerNorm (half in) -> half ---------------- */
__global__ __launch_bounds__(256)
void ln_h_kernel(const __half* __restrict__ x, const float* __restrict__ w,
                 const float* __restrict__ b, __half* __restrict__ out)
{
    __shared__ float sh[9];
    const int row = blockIdx.x;
    const int t = threadIdx.x;
    const __half2* xr = (const __half2*)(x + (size_t)row * EMB) + t * 2;

    const __half2 h0 = xr[0], h1 = xr[1];
    float v0 = __half2float(__low2half(h0)), v1 = __half2float(__high2half(h0));
    float v2 = __half2float(__low2half(h1)), v3 = __half2float(__high2half(h1));
    float mu = block_sum_1024(v0 + v1 + v2 + v3, sh) * (1.f / EMB);

    float d0 = v0 - mu, d1 = v1 - mu, d2 = v2 - mu, d3 = v3 - mu;
    float var = block_sum_1024(d0 * d0 + d1 * d1 + d2 * d2 + d3 * d3, sh) * (1.f / EMB);
    float rs = rsqrtf(var + 1e-5f);

    float4 wv = *(const float4*)(w + t * 4);
    float4 bv = *(const float4*)(b + t * 4);
    __half2* orow = (__half2*)(out + (size_t)row * EMB + t * 4);
    orow[0] = __floats2half2_rn(d0 * rs * wv.x + bv.x, d1 * rs * wv.y + bv.y);
    orow[1] = __floats2half2_rn(d2 * rs * wv.z + bv.z, d3 * rs * wv.w + bv.w);
}

/* ---------------- tensorized local attention (half in, cp.async, dbuf KV) --- */
#define AROWP 72
#define ABUF (128 * AROWP)
#define ASMEM (5 * ABUF * 2)

__global__ __launch_bounds__(256, 1)
void lattn_mma(const __half* __restrict__ qkv, __half* __restrict__ out)
{
    extern __shared__ __align__(16) __half sm[];
    const uint32_t smb = smem_u32(sm);

    const int bi = blockIdx.x;
    const int bh = blockIdx.y;
    const int b = bh >> 4, h = bh & 15;
    const int tid = threadIdx.x;
    const int wid = tid >> 5;
    const int lane = tid & 31;
    const int g = lane >> 2;
    const int tg = lane & 3;

    const __half* base = qkv + (size_t)b * SEQ * (3 * EMB);
    const int srow = tid >> 1;
    const int scol = (tid & 1) * 32;

    {
        const __half* qr = base + (size_t)(bi * WIN + srow) * (3 * EMB) + h * HD + scol;
        const uint32_t qd = smb + (uint32_t)(srow * AROWP + scol) * 2;
        #pragma unroll
        for (int i = 0; i < 4; i++)
            cp16(qd + i * 16, qr + i * 8);
        cp_commit();
    }

    auto stage_kv = [&](int sb) {
        const __half* kr = base + (size_t)(sb * WIN + srow) * (3 * EMB) + EMB + h * HD + scol;
        const __half* vr = kr + EMB;
        const int buf = sb & 1;
        const uint32_t kd = smb + (uint32_t)((1 + buf) * ABUF + srow * AROWP + scol) * 2;
        const uint32_t vd = smb + (uint32_t)((3 + buf) * ABUF + srow * AROWP + scol) * 2;
        #pragma unroll
        for (int i = 0; i < 4; i++) {
            cp16(kd + i * 16, kr + i * 8);
            cp16(vd + i * 16, vr + i * 8);
        }
        cp_commit();
    };

    const int sb_lo = (bi > 0) ? bi - 1 : 0;
    const int sb_hi = (bi < NB - 1) ? bi + 1 : NB - 1;
    stage_kv(sb_lo);

    uint32_t qa[4][4];
    float m0 = -INFINITY, m1 = -INFINITY, l0 = 0.f, l1 = 0.f;
    float o[8][4];
    #pragma unroll
    for (int i = 0; i < 8; i++)
        #pragma unroll
        for (int r = 0; r < 4; r++) o[i][r] = 0.f;

    for (int sb = sb_lo; sb <= sb_hi; sb++) {
        cp_wait<0>();
        __syncthreads();

        if (sb == sb_lo) {
            const uint32_t al = smb + (uint32_t)((wid * 16 + (lane & 15)) * AROWP) * 2
                              + (lane >> 4) * 16;
            #pragma unroll
            for (int kt = 0; kt < 4; kt++)
                ldsm_x4(qa[kt], al + kt * 32);
        }
        if (sb + 1 <= sb_hi) stage_kv(sb + 1);

        const int buf = sb & 1;

        float s[16][4];
        #pragma unroll
        for (int i = 0; i < 16; i++)
            #pragma unroll
            for (int r = 0; r < 4; r++) s[i][r] = 0.f;

        const uint32_t kb = smb + (uint32_t)((1 + buf) * ABUF) * 2
                          + (uint32_t)(((lane & 7) + ((lane >> 4) << 3)) * AROWP) * 2
                          + ((lane >> 3) & 1) * 16;
        #pragma unroll
        for (int kt = 0; kt < 4; kt++) {
            #pragma unroll
            for (int np = 0; np < 8; np++) {
                uint32_t bf[4];
                ldsm_x4(bf, kb + (uint32_t)(np * 16 * AROWP) * 2 + kt * 32);
                mma_f16(s[2 * np],     qa[kt], &bf[0]);
                mma_f16(s[2 * np + 1], qa[kt], &bf[2]);
            }
        }
        #pragma unroll
        for (int i = 0; i < 16; i++) {
            s[i][0] *= 0.125f; s[i][1] *= 0.125f;
            s[i][2] *= 0.125f; s[i][3] *= 0.125f;
        }

        float cx0 = -INFINITY, cx1 = -INFINITY;
        #pragma unroll
        for (int i = 0; i < 16; i++) {
            cx0 = fmaxf(cx0, fmaxf(s[i][0], s[i][1]));
            cx1 = fmaxf(cx1, fmaxf(s[i][2], s[i][3]));
        }
        cx0 = fmaxf(cx0, __shfl_xor_sync(0xFFFFFFFFu, cx0, 1));
        cx0 = fmaxf(cx0, __shfl_xor_sync(0xFFFFFFFFu, cx0, 2));
        cx1 = fmaxf(cx1, __shfl_xor_sync(0xFFFFFFFFu, cx1, 1));
        cx1 = fmaxf(cx1, __shfl_xor_sync(0xFFFFFFFFu, cx1, 2));
        const float mn0 = fmaxf(m0, cx0);
        const float mn1 = fmaxf(m1, cx1);
        const float cr0 = __expf(m0 - mn0);
        const float cr1 = __expf(m1 - mn1);
        l0 *= cr0; l1 *= cr1;
        #pragma unroll
        for (int i = 0; i < 8; i++) {
            o[i][0] *= cr0; o[i][1] *= cr0;
            o[i][2] *= cr1; o[i][3] *= cr1;
        }
        float sm0 = 0.f, sm1 = 0.f;
        #pragma unroll
        for (int i = 0; i < 16; i++) {
            s[i][0] = __expf(s[i][0] - mn0);
            s[i][1] = __expf(s[i][1] - mn0);
            s[i][2] = __expf(s[i][2] - mn1);
            s[i][3] = __expf(s[i][3] - mn1);
            sm0 += s[i][0] + s[i][1];
            sm1 += s[i][2] + s[i][3];
        }
        sm0 += __shfl_xor_sync(0xFFFFFFFFu, sm0, 1);
        sm0 += __shfl_xor_sync(0xFFFFFFFFu, sm0, 2);
        sm1 += __shfl_xor_sync(0xFFFFFFFFu, sm1, 1);
        sm1 += __shfl_xor_sync(0xFFFFFFFFu, sm1, 2);
        l0 += sm0; l1 += sm1;
        m0 = mn0; m1 = mn1;

        const uint32_t vb = smb + (uint32_t)((3 + buf) * ABUF) * 2
                          + (uint32_t)((lane & 15) * AROWP) * 2 + (lane >> 4) * 16;
        #pragma unroll
        for (int kt = 0; kt < 8; kt++) {
            __half2 t0 = __floats2half2_rn(s[2 * kt][0], s[2 * kt][1]);
            __half2 t1 = __floats2half2_rn(s[2 * kt][2], s[2 * kt][3]);
            __half2 t2 = __floats2half2_rn(s[2 * kt + 1][0], s[2 * kt + 1][1]);
            __half2 t3 = __floats2half2_rn(s[2 * kt + 1][2], s[2 * kt + 1][3]);
            uint32_t pa[4];
            pa[0] = *(uint32_t*)&t0;
            pa[1] = *(uint32_t*)&t1;
            pa[2] = *(uint32_t*)&t2;
            pa[3] = *(uint32_t*)&t3;
            #pragma unroll
            for (int db = 0; db < 4; db++) {
                uint32_t bt[4];
                ldsm_x4_t(bt, vb + (uint32_t)(kt * 16 * AROWP) * 2 + db * 32);
                mma_f16(o[db * 2],     pa, &bt[0]);
                mma_f16(o[db * 2 + 1], pa, &bt[2]);
            }
        }
    }

    const float iv0 = 1.f / l0;
    const float iv1 = 1.f / l1;
    const int r0 = bi * WIN + wid * 16 + g;
    __half2* out0 = (__half2*)(out + ((size_t)(b * SEQ + r0)) * EMB + h * HD);
    __half2* out1 = (__half2*)(out + ((size_t)(b * SEQ + r0 + 8)) * EMB + h * HD);
    #pragma unroll
    for (int nt = 0; nt < 8; nt++) {
        const int c = (nt * 8 + tg * 2) >> 1;
        out0[c] = __floats2half2_rn(o[nt][0] * iv0, o[nt][1] * iv0);
        out1[c] = __floats2half2_rn(o[nt][2] * iv1, o[nt][3] * iv1);
    }
}

/* ---------------- launch ---------------- */
extern "C" void kernel_launch(void* const* d_in, const int* in_sizes, int n_in,
                              void* d_out, int out_size)
{
    const float* x     = (const float*)d_in[0];
    const float* ln1w  = (const float*)d_in[1];
    const float* ln1b  = (const float*)d_in[2];
    const float* qkvw  = (const float*)d_in[3];
    const float* qkvb  = (const float*)d_in[4];
    const float* projw = (const float*)d_in[5];
    const float* projb = (const float*)d_in[6];
    const float* ln2w  = (const float*)d_in[7];
    const float* ln2b  = (const float*)d_in[8];
    const float* fc1w  = (const float*)d_in[9];
    const float* fc1b  = (const float*)d_in[10];
    const float* fc2w  = (const float*)d_in[11];
    const float* fc2b  = (const float*)d_in[12];
    float* out = (float*)d_out;

    __half *xnh, *qkvh, *attnh, *x1h, *hbufh, *wqh, *wph, *w1h, *w2h;
    cudaGetSymbolAddress((void**)&xnh,   g_xnh);
    cudaGetSymbolAddress((void**)&qkvh,  g_qkvh);
    cudaGetSymbolAddress((void**)&attnh, g_attnh);
    cudaGetSymbolAddress((void**)&x1h,   g_x1h);
    cudaGetSymbolAddress((void**)&hbufh, g_hbufh);
    cudaGetSymbolAddress((void**)&wqh,   g_wqh);
    cudaGetSymbolAddress((void**)&wph,   g_wph);
    cudaGetSymbolAddress((void**)&w1h,   g_w1h);
    cudaGetSymbolAddress((void**)&w2h,   g_w2h);

    cudaFuncSetAttribute(hgemm<EPI_NONE, 1, 0>, cudaFuncAttributeMaxDynamicSharedMemorySize, HSMEM);
    cudaFuncSetAttribute(hgemm<EPI_ADD, 1, 0>,  cudaFuncAttributeMaxDynamicSharedMemorySize, HSMEM);
    cudaFuncSetAttribute(hgemm<EPI_GELU, 1, 0>, cudaFuncAttributeMaxDynamicSharedMemorySize, HSMEM);
    cudaFuncSetAttribute(hgemm<EPI_ADD, 0, 1>,  cudaFuncAttributeMaxDynamicSharedMemorySize, HSMEM);
    cudaFuncSetAttribute(lattn_mma, cudaFuncAttributeMaxDynamicSharedMemorySize, ASMEM);

    /* all four weight conversions in one launch */
    w2h_all<<<(W_TOT + 255) / 256, 256>>>(qkvw, wqh, projw, wph, fc1w, w1h, fc2w, w2h);

    /* 1. LN1 -> half */
    ln_kernel<<<M_TOK, 256>>>(x, ln1w, ln1b, xnh);
    /* 2. qkv (half out) */
    hgemm<EPI_NONE, 1, 0><<<dim3(3 * EMB / BN, M_TOK / BM), 256, HSMEM>>>(
        xnh, wqh, qkvb, nullptr, qkvh, M_TOK, 3 * EMB, EMB);
    /* 3. attention -> half */
    lattn_mma<<<dim3(NB, BATCH * HEADS), 256, ASMEM>>>(qkvh, attnh);
    /* 4. x1 = x + attn@wp^T + b  (fp32 residual in, HALF out) */
    hgemm<EPI_ADD, 1, 0><<<dim3(EMB / BN, M_TOK / BM), 256, HSMEM>>>(
        attnh, wph, projb, x, x1h, M_TOK, EMB, EMB);
    /* 5. LN2 (half in) -> half */
    ln_h_kernel<<<M_TOK, 256>>>(x1h, ln2w, ln2b, xnh);
    /* 6. hbuf = gelu(...) -> half */
    hgemm<EPI_GELU, 1, 0><<<dim3(DFF / BN, M_TOK / BM), 256, HSMEM>>>(
        xnh, w1h, fc1b, nullptr, hbufh, M_TOK, DFF, EMB);
    /* 7. out = x1h + hbuf@w2^T + b  (half residual, fp32 out) */
    hgemm<EPI_ADD, 0, 1><<<dim3(EMB / BN, M_TOK / BM), 256, HSMEM>>>(
        hbufh, w2h, fc2b, x1h, out, M_TOK, EMB, DFF);
}